// round 10
// baseline (speedup 1.0000x reference)
#include <cuda_runtime.h>
#include <math.h>
#include <stdint.h>

// Problem constants
#define HH 96
#define WWID 96
#define HWSZ (HH * WWID)          // 9216
#define BATCH 8
#define P_TOT (BATCH * HWSZ)      // 73728 pixels
#define C_IN 256
#define C_O 128

// Scratch (device globals — allocation-free per harness rules)
__device__ __align__(16) float g_theta[(size_t)P_TOT * C_O];
__device__ __align__(16) float g_phi  [(size_t)P_TOT * C_O];
__device__ __align__(16) float g_g    [(size_t)P_TOT * C_O];
__device__ __align__(16) float g_wa   [(size_t)P_TOT * C_O];   // stored tf32-rounded
__device__ __align__(16) float g_w3   [3 * C_O * C_IN];        // tf32 w_theta|w_phi|w_g
__device__ __align__(16) float g_wb   [C_IN * C_O];            // tf32 w_back
__device__ float g_tnorm[P_TOT];
__device__ float g_pnorm[P_TOT];

__device__ __forceinline__ uint32_t f2tf32(float x) {
    uint32_t r;
    asm("cvt.rna.tf32.f32 %0, %1;" : "=r"(r) : "f"(x));
    return r;
}

__device__ __forceinline__ void mma_tf32(float c[4],
                                         uint32_t a0, uint32_t a1, uint32_t a2, uint32_t a3,
                                         uint32_t b0, uint32_t b1) {
    asm volatile(
        "mma.sync.aligned.m16n8k8.row.col.f32.tf32.tf32.f32 "
        "{%0,%1,%2,%3},{%4,%5,%6,%7},{%8,%9},{%0,%1,%2,%3};"
        : "+f"(c[0]), "+f"(c[1]), "+f"(c[2]), "+f"(c[3])
        : "r"(a0), "r"(a1), "r"(a2), "r"(a3), "r"(b0), "r"(b1));
}

__device__ __forceinline__ void ldsm_x4(uint32_t& r0, uint32_t& r1, uint32_t& r2, uint32_t& r3,
                                        uint32_t addr) {
    asm volatile("ldmatrix.sync.aligned.m8n8.x4.shared.b16 {%0,%1,%2,%3}, [%4];"
                 : "=r"(r0), "=r"(r1), "=r"(r2), "=r"(r3) : "r"(addr));
}

__device__ __forceinline__ void ldsm_x2(uint32_t& r0, uint32_t& r1, uint32_t addr) {
    asm volatile("ldmatrix.sync.aligned.m8n8.x2.shared.b16 {%0,%1}, [%2];"
                 : "=r"(r0), "=r"(r1) : "r"(addr));
}

#define CP16_CA(dst, src) \
    asm volatile("cp.async.ca.shared.global [%0], [%1], 16;" :: "r"(dst), "l"(src))
#define CP16_CG(dst, src) \
    asm volatile("cp.async.cg.shared.global [%0], [%1], 16;" :: "r"(dst), "l"(src))
#define CP_COMMIT() asm volatile("cp.async.commit_group;")
#define CP_WAIT2()  asm volatile("cp.async.wait_group 2;")
#define CP_WAIT1()  asm volatile("cp.async.wait_group 1;")
#define CP_WAIT0()  asm volatile("cp.async.wait_group 0;")

// ---------------------------------------------------------------------------
// Setup: tf32-round all weights once.
// ---------------------------------------------------------------------------
__global__ void cvt_weights(const float* __restrict__ wt, const float* __restrict__ wp,
                            const float* __restrict__ wg, const float* __restrict__ wb)
{
    int i = blockIdx.x * 256 + threadIdx.x;      // 0 .. 32767
    g_w3[i]         = __uint_as_float(f2tf32(wt[i]));
    g_w3[32768 + i] = __uint_as_float(f2tf32(wp[i]));
    g_w3[65536 + i] = __uint_as_float(f2tf32(wg[i]));
    g_wb[i]         = __uint_as_float(f2tf32(wb[i]));
}

// ---------------------------------------------------------------------------
// Pass 1 (tensor, 4-stage cp.async): theta/phi/g = W(128x256)@x + bias.
// grid = (3, 576): wsel fastest -> 3 co-resident blocks share the x tile in L2.
// Norms of theta/phi computed in the epilogue.
// dyn smem: 4*(2560+2176) + 128 = 19072 floats = 76288 B.
// ---------------------------------------------------------------------------
__global__ __launch_bounds__(256, 2) void pass1_gemm(
    const float* __restrict__ x,
    const float* __restrict__ b_theta, const float* __restrict__ b_phi,
    const float* __restrict__ b_g)
{
    extern __shared__ __align__(16) float sm[];
    float* As = sm;                    // [4][128][20]
    float* Bs = sm + 4 * 2560;         // [4][16][136]
    float (*stage)[68] = (float(*)[68])sm;
    float* part = sm + 18944;          // [128] per-px sum of squares

    const int tid = threadIdx.x;
    const int lane = tid & 31;
    const int warp = tid >> 5;
    const int warp_m = warp >> 2;
    const int warp_n = warp & 3;
    const int q = lane >> 2;
    const int kl = lane & 3;

    const int wsel = blockIdx.x;
    const int p0 = blockIdx.y * 128;
    const int b = p0 / HWSZ;
    const int hw0 = p0 % HWSZ;

    const float* wsrc = g_w3 + wsel * 32768;
    const float* bias = (wsel == 0) ? b_theta : ((wsel == 1) ? b_phi : b_g);
    float* outp       = (wsel == 0) ? g_theta : ((wsel == 1) ? g_phi : g_g);

    float acc[4][4][4];
#pragma unroll
    for (int mt = 0; mt < 4; ++mt)
#pragma unroll
        for (int nt = 0; nt < 4; ++nt)
#pragma unroll
            for (int i = 0; i < 4; ++i) acc[mt][nt][i] = 0.f;

    const int am   = tid >> 1;
    const int akq0 = (tid & 1) * 2;
    const int bk   = tid >> 4;
    const int bpq0 = (tid & 15) * 2;

    const uint32_t as_base = (uint32_t)__cvta_generic_to_shared(As);
    const uint32_t bs_base = (uint32_t)__cvta_generic_to_shared(Bs);
    const uint32_t a_dst0 = as_base + 4u * (uint32_t)(am * 20 + akq0 * 4);
    const uint32_t b_dst0 = bs_base + 4u * (uint32_t)(bk * 136 + bpq0 * 4);
    const float* a_src0 = wsrc + am * C_IN + akq0 * 4;
    const float* b_src0 = x + (size_t)(b * C_IN + bk) * HWSZ + hw0 + bpq0 * 4;

    const uint32_t a_frag = as_base + 4u * ((uint32_t)(warp_m * 64 + (lane & 15)) * 20u
                                            + (uint32_t)(lane >> 4) * 4u);

#define P1_ISSUE(buf, k0) do { \
    const float* as_ = a_src0 + (k0); \
    uint32_t ad_ = a_dst0 + (uint32_t)(buf) * 10240u; \
    CP16_CA(ad_,      as_); \
    CP16_CA(ad_ + 16, as_ + 4); \
    const float* bs_ = b_src0 + (size_t)(k0) * HWSZ; \
    uint32_t bd_ = b_dst0 + (uint32_t)(buf) * 8704u; \
    CP16_CG(bd_,      bs_); \
    CP16_CG(bd_ + 16, bs_ + 4); \
} while (0)

    P1_ISSUE(0, 0);  CP_COMMIT();
    P1_ISSUE(1, 16); CP_COMMIT();
    P1_ISSUE(2, 32); CP_COMMIT();

#pragma unroll 4
    for (int kt = 0; kt < 16; ++kt) {
        const int buf = kt & 3;
        CP_WAIT2();
        __syncthreads();
        if (kt + 3 < 16) P1_ISSUE((kt + 3) & 3, (kt + 3) * 16);
        CP_COMMIT();

#pragma unroll
        for (int ks = 0; ks < 16; ks += 8) {
            uint32_t af[4][4];
#pragma unroll
            for (int mt = 0; mt < 4; ++mt)
                ldsm_x4(af[mt][0], af[mt][1], af[mt][2], af[mt][3],
                        a_frag + (uint32_t)buf * 10240u + (uint32_t)mt * 1280u + (uint32_t)ks * 4u);
            uint32_t bf[4][2];
            const int kq = ks + kl;
#pragma unroll
            for (int nt = 0; nt < 4; ++nt) {
                int pc = warp_n * 32 + nt * 8 + q;
                bf[nt][0] = __float_as_uint(Bs[buf * 2176 + kq * 136 + pc]);
                bf[nt][1] = __float_as_uint(Bs[buf * 2176 + (kq + 4) * 136 + pc]);
            }
#pragma unroll
            for (int mt = 0; mt < 4; ++mt)
#pragma unroll
                for (int nt = 0; nt < 4; ++nt)
                    mma_tf32(acc[mt][nt], af[mt][0], af[mt][1], af[mt][2], af[mt][3],
                             bf[nt][0], bf[nt][1]);
        }
        __syncthreads();
    }
#undef P1_ISSUE

    float bias_v[4][2];
#pragma unroll
    for (int mt = 0; mt < 4; ++mt)
#pragma unroll
        for (int hi = 0; hi < 2; ++hi)
            bias_v[mt][hi] = bias[warp_m * 64 + mt * 16 + q + hi * 8];

    if (tid < 128) part[tid] = 0.f;

    // Epilogue: stage [px][64ch], coalesced stores + fused norm reduction
#pragma unroll
    for (int h = 0; h < 2; ++h) {
        __syncthreads();
        if (warp_m == h) {
#pragma unroll
            for (int mt = 0; mt < 4; ++mt)
#pragma unroll
                for (int nt = 0; nt < 4; ++nt)
#pragma unroll
                    for (int i = 0; i < 4; ++i) {
                        int px = warp_n * 32 + nt * 8 + 2 * kl + (i & 1);
                        int ch = mt * 16 + q + 8 * (i >> 1);
                        stage[px][ch] = acc[mt][nt][i] + bias_v[mt][i >> 1];
                    }
        }
        __syncthreads();
#pragma unroll
        for (int it = 0; it < 8; ++it) {
            int g = tid + it * 256;
            int px = g >> 4;
            int f  = g & 15;
            float4 v = *(float4*)&stage[px][f * 4];
            ((float4*)outp)[(size_t)(p0 + px) * 32 + h * 16 + f] = v;
            if (wsel < 2) {
                float sq = v.x * v.x + v.y * v.y + v.z * v.z + v.w * v.w;
                sq += __shfl_xor_sync(0xffffffffu, sq, 1);
                sq += __shfl_xor_sync(0xffffffffu, sq, 2);
                sq += __shfl_xor_sync(0xffffffffu, sq, 4);
                sq += __shfl_xor_sync(0xffffffffu, sq, 8);
                if (f == 0) part[px] += sq;   // same thread owns px across h: no race
            }
        }
    }
    __syncthreads();
    if (wsel < 2 && tid < 128) {
        float* np = (wsel == 0) ? g_tnorm : g_pnorm;
        np[p0 + tid] = sqrtf(part[tid]);
    }
}

// ---------------------------------------------------------------------------
// Pass 2 (smem-tiled, overlapped): block = 32-px row strip. Phi AND g
// neighborhoods issued as two cp.async groups up front; wait_group 1 releases
// phi (g still in flight behind score computation), wait_group 0 before the
// weighted average. 2 CTAs/SM.
// dyn smem: 2*13056 (tiles) + 320 (wt) + 104 (pnorm) = 26536 fl = 106144 B
// grid = P_TOT/32, block 256 (8 warps x 4 px each).
// ---------------------------------------------------------------------------
__global__ __launch_bounds__(256) void pass2_attn()
{
    extern __shared__ __align__(16) float psm[];
    float* tphi = psm;                  // [102][128]
    float* tg   = psm + 13056;          // [102][128]
    float* wt_s = psm + 26112;          // [32][10]
    float* pn_s = psm + 26432;          // [102]

    const int tid  = threadIdx.x;
    const int warp = tid >> 5;
    const int lane = tid & 31;

    const int p0 = blockIdx.x * 32;
    const int b  = p0 / HWSZ;
    const int hw = p0 % HWSZ;
    const int h  = hw / WWID;
    const int w0 = hw % WWID;

    const float4* th4 = (const float4*)g_theta;
    const uint32_t phib = (uint32_t)__cvta_generic_to_shared(tphi);
    const uint32_t gb   = (uint32_t)__cvta_generic_to_shared(tg);

    // Precompute clamped source pixel offsets (13 slots per thread max)
    size_t srcoff[13];
    int nslots = 0;
#pragma unroll 1
    for (int idx = tid; idx < 3264; idx += 256) {
        int pxl = idx >> 5;             // 0..101
        int r = pxl / 34, c = pxl % 34;
        int hr = min(max(h + r - 1, 0), HH - 1);
        int wc = min(max(w0 + c - 1, 0), WWID - 1);
        srcoff[nslots++] = (((size_t)(b * HWSZ + hr * WWID + wc)) << 7) + (size_t)(idx & 31) * 4;
    }

    // Group 1: phi neighborhood
    {
        int s = 0;
#pragma unroll 1
        for (int idx = tid; idx < 3264; idx += 256)
            CP16_CG(phib + (uint32_t)idx * 16u, g_phi + srcoff[s++]);
    }
    CP_COMMIT();
    // Group 2: g neighborhood (lands while scores are computed)
    {
        int s = 0;
#pragma unroll 1
        for (int idx = tid; idx < 3264; idx += 256)
            CP16_CG(gb + (uint32_t)idx * 16u, g_g + srcoff[s++]);
    }
    CP_COMMIT();

    if (tid < 102) {
        int r = tid / 34, c = tid % 34;
        int hr = min(max(h + r - 1, 0), HH - 1);
        int wc = min(max(w0 + c - 1, 0), WWID - 1);
        pn_s[tid] = g_pnorm[b * HWSZ + hr * WWID + wc];
    }

    CP_WAIT1();          // phi ready; g group may still be in flight
    __syncthreads();

    // ---- scores + softmax per pixel (4 px per warp) ----
#pragma unroll
    for (int jj = 0; jj < 4; ++jj) {
        int pxl = warp * 4 + jj;        // 0..31
        int p = p0 + pxl;
        float4 th = th4[(size_t)p * 32 + lane];
        float tn = g_tnorm[p];

        float d[9];
#pragma unroll
        for (int n = 0; n < 9; ++n) {
            int di = n / 3, dj = n % 3;
            const float4 ph = *(const float4*)&tphi[((di * 34 + pxl + dj) * 32 + lane) * 4];
            d[n] = th.x * ph.x + th.y * ph.y + th.z * ph.z + th.w * ph.w;
        }
#pragma unroll
        for (int off = 16; off; off >>= 1)
#pragma unroll
            for (int n = 0; n < 9; ++n)
                d[n] += __shfl_xor_sync(0xffffffffu, d[n], off);

        float s = 0.f;
#pragma unroll
        for (int n = 0; n < 9; ++n) {
            int di = n / 3, dj = n % 3;
            float den = fmaxf(tn * pn_s[di * 34 + pxl + dj], 1e-8f);
            d[n] = __expf(d[n] / den);      // scores bounded in [-1,1]: no max-shift
            s += d[n];
        }
        float inv = 1.f / s;
        if (lane == 0) {
#pragma unroll
            for (int n = 0; n < 9; ++n) wt_s[pxl * 10 + n] = d[n] * inv;
        }
    }

    CP_WAIT0();          // g ready (mostly already landed)
    __syncthreads();

    // ---- weighted average ----
#pragma unroll
    for (int jj = 0; jj < 4; ++jj) {
        int pxl = warp * 4 + jj;
        int p = p0 + pxl;
        float wt[9];
#pragma unroll
        for (int n = 0; n < 9; ++n) wt[n] = wt_s[pxl * 10 + n];

        float4 acc = make_float4(0.f, 0.f, 0.f, 0.f);
#pragma unroll
        for (int n = 0; n < 9; ++n) {
            int di = n / 3, dj = n % 3;
            const float4 gv = *(const float4*)&tg[((di * 34 + pxl + dj) * 32 + lane) * 4];
            acc.x += wt[n] * gv.x; acc.y += wt[n] * gv.y;
            acc.z += wt[n] * gv.z; acc.w += wt[n] * gv.w;
        }
        uint4 o;
        o.x = f2tf32(acc.x); o.y = f2tf32(acc.y);
        o.z = f2tf32(acc.z); o.w = f2tf32(acc.w);
        ((uint4*)g_wa)[(size_t)p * 32 + lane] = o;
    }
}

// ---------------------------------------------------------------------------
// Pass 3 (tensor, 4-stage cp.async, R5 form): out = x + W_back@wa + b_back.
// Tile 128 ch x 128 px. dyn smem: 4*2560*2 = 20480 floats = 81920 B.
// grid = (576, 2)
// ---------------------------------------------------------------------------
__global__ __launch_bounds__(256, 2) void pass3_gemm(
    const float* __restrict__ x,
    const float* __restrict__ b_back,
    float* __restrict__ out)
{
    extern __shared__ __align__(16) float sm[];
    float* As = sm;                    // [4][128][20]
    float* Bs = sm + 4 * 2560;         // [4][128][20]
    float (*stage)[132] = (float(*)[132])sm;

    const int tid = threadIdx.x;
    const int lane = tid & 31;
    const int warp = tid >> 5;
    const int warp_m = warp >> 2;
    const int warp_n = warp & 3;
    const int q = lane >> 2;
    const int kl = lane & 3;

    const int p0 = blockIdx.x * 128;
    const int b = p0 / HWSZ;
    const int hw0 = p0 % HWSZ;
    const int c0 = blockIdx.y * 128;

    float acc[4][4][4];
#pragma unroll
    for (int mt = 0; mt < 4; ++mt)
#pragma unroll
        for (int nt = 0; nt < 4; ++nt)
#pragma unroll
            for (int i = 0; i < 4; ++i) acc[mt][nt][i] = 0.f;

    const int am   = tid >> 1;
    const int akq0 = (tid & 1) * 2;

    const uint32_t as_base = (uint32_t)__cvta_generic_to_shared(As);
    const uint32_t bs_base = (uint32_t)__cvta_generic_to_shared(Bs);
    const uint32_t a_dst0 = as_base + 4u * (uint32_t)(am * 20 + akq0 * 4);
    const uint32_t b_dst0 = bs_base + 4u * (uint32_t)(am * 20 + akq0 * 4);
    const float* a_src0 = g_wb + (size_t)(c0 + am) * C_O + akq0 * 4;
    const float* b_src0 = g_wa + (size_t)(p0 + am) * C_O + akq0 * 4;

    const uint32_t a_frag = as_base + 4u * ((uint32_t)(warp_m * 64 + (lane & 15)) * 20u
                                            + (uint32_t)(lane >> 4) * 4u);
    const uint32_t b_frag = bs_base + 4u * ((uint32_t)(warp_n * 32 + (lane & 7)) * 20u
                                            + (uint32_t)((lane >> 3) & 1) * 4u);

#define P3_ISSUE(buf, k0) do { \
    const float* as_ = a_src0 + (k0); \
    uint32_t ad_ = a_dst0 + (uint32_t)(buf) * 10240u; \
    CP16_CA(ad_,      as_); \
    CP16_CA(ad_ + 16, as_ + 4); \
    const float* bs_ = b_src0 + (k0); \
    uint32_t bd_ = b_dst0 + (uint32_t)(buf) * 10240u; \
    CP16_CG(bd_,      bs_); \
    CP16_CG(bd_ + 16, bs_ + 4); \
} while (0)

    P3_ISSUE(0, 0);  CP_COMMIT();
    P3_ISSUE(1, 16); CP_COMMIT();
    P3_ISSUE(2, 32); CP_COMMIT();

#pragma unroll 4
    for (int kt = 0; kt < 8; ++kt) {
        const int buf = kt & 3;
        CP_WAIT2();
        __syncthreads();
        if (kt + 3 < 8) P3_ISSUE((kt + 3) & 3, (kt + 3) * 16);
        CP_COMMIT();

#pragma unroll
        for (int ks = 0; ks < 16; ks += 8) {
            uint32_t af[4][4];
#pragma unroll
            for (int mt = 0; mt < 4; ++mt)
                ldsm_x4(af[mt][0], af[mt][1], af[mt][2], af[mt][3],
                        a_frag + (uint32_t)buf * 10240u + (uint32_t)mt * 1280u + (uint32_t)ks * 4u);
            uint32_t bf[4][2];
#pragma unroll
            for (int nt = 0; nt < 4; ++nt)
                ldsm_x2(bf[nt][0], bf[nt][1],
                        b_frag + (uint32_t)buf * 10240u + (uint32_t)nt * 640u + (uint32_t)ks * 4u);
#pragma unroll
            for (int mt = 0; mt < 4; ++mt)
#pragma unroll
                for (int nt = 0; nt < 4; ++nt)
                    mma_tf32(acc[mt][nt], af[mt][0], af[mt][1], af[mt][2], af[mt][3],
                             bf[nt][0], bf[nt][1]);
        }
        __syncthreads();
    }
#undef P3_ISSUE

    // Epilogue: stage [ch][px], then coalesced residual-add + store
#pragma unroll
    for (int h = 0; h < 2; ++h) {
        __syncthreads();
        if (warp_m == h) {
#pragma unroll
            for (int mt = 0; mt < 4; ++mt)
#pragma unroll
                for (int nt = 0; nt < 4; ++nt)
#pragma unroll
                    for (int hi = 0; hi < 2; ++hi) {
                        int ch = mt * 16 + q + 8 * hi;
                        int px = warp_n * 32 + nt * 8 + 2 * kl;
                        float2 v2 = make_float2(acc[mt][nt][hi * 2], acc[mt][nt][hi * 2 + 1]);
                        *(float2*)&stage[ch][px] = v2;
                    }
        }
        __syncthreads();
#pragma unroll
        for (int it = 0; it < 8; ++it) {
            int g = tid + it * 256;
            int ch = g >> 5;
            int f  = g & 31;
            int c  = c0 + h * 64 + ch;
            size_t gi = (((size_t)(b * C_IN + c)) * HWSZ + hw0) / 4 + f;
            float4 s = *(float4*)&stage[ch][f * 4];
            float4 xv = ((const float4*)x)[gi];
            float bb = b_back[c];
            float4 o4;
            o4.x = xv.x + bb + s.x;
            o4.y = xv.y + bb + s.y;
            o4.z = xv.z + bb + s.z;
            o4.w = xv.w + bb + s.w;
            ((float4*)out)[gi] = o4;
        }
    }
}

// ---------------------------------------------------------------------------
extern "C" void kernel_launch(void* const* d_in, const int* in_sizes, int n_in,
                              void* d_out, int out_size)
{
    const float* x       = (const float*)d_in[0];
    const float* w_theta = (const float*)d_in[1];
    const float* b_theta = (const float*)d_in[2];
    const float* w_phi   = (const float*)d_in[3];
    const float* b_phi   = (const float*)d_in[4];
    const float* w_g     = (const float*)d_in[5];
    const float* b_g     = (const float*)d_in[6];
    const float* w_back  = (const float*)d_in[7];
    const float* b_back  = (const float*)d_in[8];
    float* out = (float*)d_out;

    const int p1_smem = 19072 * 4;   // 76288 B
    const int p2_smem = 26536 * 4;   // 106144 B
    const int p3_smem = 20480 * 4;   // 81920 B
    cudaFuncSetAttribute(pass1_gemm, cudaFuncAttributeMaxDynamicSharedMemorySize, p1_smem);
    cudaFuncSetAttribute(pass2_attn, cudaFuncAttributeMaxDynamicSharedMemorySize, p2_smem);
    cudaFuncSetAttribute(pass3_gemm, cudaFuncAttributeMaxDynamicSharedMemorySize, p3_smem);

    cvt_weights<<<128, 256>>>(w_theta, w_phi, w_g, w_back);

    dim3 g1(3, P_TOT / 128, 1);
    pass1_gemm<<<g1, 256, p1_smem>>>(x, b_theta, b_phi, b_g);

    pass2_attn<<<P_TOT / 32, 256, p2_smem>>>();

    dim3 g3(P_TOT / 128, 2, 1);
    pass3_gemm<<<g3, 256, p3_smem>>>(x, b_back, out);
}

// round 11
// speedup vs baseline: 1.1947x; 1.1947x over previous
#include <cuda_runtime.h>
#include <math.h>
#include <stdint.h>

// Problem constants
#define HH 96
#define WWID 96
#define HWSZ (HH * WWID)          // 9216
#define BATCH 8
#define P_TOT (BATCH * HWSZ)      // 73728 pixels
#define C_IN 256
#define C_O 128

// Scratch (device globals — allocation-free per harness rules)
__device__ __align__(16) float g_theta[(size_t)P_TOT * C_O];
__device__ __align__(16) float g_phi  [(size_t)P_TOT * C_O];
__device__ __align__(16) float g_g    [(size_t)P_TOT * C_O];
__device__ __align__(16) float g_wa   [(size_t)P_TOT * C_O];   // stored tf32-rounded
__device__ __align__(16) float g_w3   [3 * C_O * C_IN];        // tf32 w_theta|w_phi|w_g
__device__ __align__(16) float g_wb   [C_IN * C_O];            // tf32 w_back
__device__ float g_tnorm[P_TOT];
__device__ float g_pnorm[P_TOT];

__device__ __forceinline__ uint32_t f2tf32(float x) {
    uint32_t r;
    asm("cvt.rna.tf32.f32 %0, %1;" : "=r"(r) : "f"(x));
    return r;
}

__device__ __forceinline__ void mma_tf32(float c[4],
                                         uint32_t a0, uint32_t a1, uint32_t a2, uint32_t a3,
                                         uint32_t b0, uint32_t b1) {
    asm volatile(
        "mma.sync.aligned.m16n8k8.row.col.f32.tf32.tf32.f32 "
        "{%0,%1,%2,%3},{%4,%5,%6,%7},{%8,%9},{%0,%1,%2,%3};"
        : "+f"(c[0]), "+f"(c[1]), "+f"(c[2]), "+f"(c[3])
        : "r"(a0), "r"(a1), "r"(a2), "r"(a3), "r"(b0), "r"(b1));
}

__device__ __forceinline__ void ldsm_x4(uint32_t& r0, uint32_t& r1, uint32_t& r2, uint32_t& r3,
                                        uint32_t addr) {
    asm volatile("ldmatrix.sync.aligned.m8n8.x4.shared.b16 {%0,%1,%2,%3}, [%4];"
                 : "=r"(r0), "=r"(r1), "=r"(r2), "=r"(r3) : "r"(addr));
}

__device__ __forceinline__ void ldsm_x2(uint32_t& r0, uint32_t& r1, uint32_t addr) {
    asm volatile("ldmatrix.sync.aligned.m8n8.x2.shared.b16 {%0,%1}, [%2];"
                 : "=r"(r0), "=r"(r1) : "r"(addr));
}

#define CP16_CA(dst, src) \
    asm volatile("cp.async.ca.shared.global [%0], [%1], 16;" :: "r"(dst), "l"(src))
#define CP16_CG(dst, src) \
    asm volatile("cp.async.cg.shared.global [%0], [%1], 16;" :: "r"(dst), "l"(src))
#define CP_COMMIT() asm volatile("cp.async.commit_group;")
#define CP_WAIT2()  asm volatile("cp.async.wait_group 2;")
#define CP_WAIT1()  asm volatile("cp.async.wait_group 1;")
#define CP_WAIT0()  asm volatile("cp.async.wait_group 0;")

// ---------------------------------------------------------------------------
// Setup: tf32-round all weights once.
// ---------------------------------------------------------------------------
__global__ void cvt_weights(const float* __restrict__ wt, const float* __restrict__ wp,
                            const float* __restrict__ wg, const float* __restrict__ wb)
{
    int i = blockIdx.x * 256 + threadIdx.x;      // 0 .. 32767
    g_w3[i]         = __uint_as_float(f2tf32(wt[i]));
    g_w3[32768 + i] = __uint_as_float(f2tf32(wp[i]));
    g_w3[65536 + i] = __uint_as_float(f2tf32(wg[i]));
    g_wb[i]         = __uint_as_float(f2tf32(wb[i]));
}

// ---------------------------------------------------------------------------
// Pass 1 (tensor, 4-stage cp.async): theta/phi/g = W(128x256)@x + bias.
// grid = (3, 576): wsel fastest -> 3 co-resident blocks share the x tile in L2.
// Norms of theta/phi computed in the epilogue.
// dyn smem: 4*(2560+2176) + 128 = 19072 floats = 76288 B.
// ---------------------------------------------------------------------------
__global__ __launch_bounds__(256, 2) void pass1_gemm(
    const float* __restrict__ x,
    const float* __restrict__ b_theta, const float* __restrict__ b_phi,
    const float* __restrict__ b_g)
{
    extern __shared__ __align__(16) float sm[];
    float* As = sm;                    // [4][128][20]
    float* Bs = sm + 4 * 2560;         // [4][16][136]
    float (*stage)[68] = (float(*)[68])sm;
    float* part = sm + 18944;          // [128] per-px sum of squares

    const int tid = threadIdx.x;
    const int lane = tid & 31;
    const int warp = tid >> 5;
    const int warp_m = warp >> 2;
    const int warp_n = warp & 3;
    const int q = lane >> 2;
    const int kl = lane & 3;

    const int wsel = blockIdx.x;
    const int p0 = blockIdx.y * 128;
    const int b = p0 / HWSZ;
    const int hw0 = p0 % HWSZ;

    const float* wsrc = g_w3 + wsel * 32768;
    const float* bias = (wsel == 0) ? b_theta : ((wsel == 1) ? b_phi : b_g);
    float* outp       = (wsel == 0) ? g_theta : ((wsel == 1) ? g_phi : g_g);

    float acc[4][4][4];
#pragma unroll
    for (int mt = 0; mt < 4; ++mt)
#pragma unroll
        for (int nt = 0; nt < 4; ++nt)
#pragma unroll
            for (int i = 0; i < 4; ++i) acc[mt][nt][i] = 0.f;

    const int am   = tid >> 1;
    const int akq0 = (tid & 1) * 2;
    const int bk   = tid >> 4;
    const int bpq0 = (tid & 15) * 2;

    const uint32_t as_base = (uint32_t)__cvta_generic_to_shared(As);
    const uint32_t bs_base = (uint32_t)__cvta_generic_to_shared(Bs);
    const uint32_t a_dst0 = as_base + 4u * (uint32_t)(am * 20 + akq0 * 4);
    const uint32_t b_dst0 = bs_base + 4u * (uint32_t)(bk * 136 + bpq0 * 4);
    const float* a_src0 = wsrc + am * C_IN + akq0 * 4;
    const float* b_src0 = x + (size_t)(b * C_IN + bk) * HWSZ + hw0 + bpq0 * 4;

    const uint32_t a_frag = as_base + 4u * ((uint32_t)(warp_m * 64 + (lane & 15)) * 20u
                                            + (uint32_t)(lane >> 4) * 4u);

#define P1_ISSUE(buf, k0) do { \
    const float* as_ = a_src0 + (k0); \
    uint32_t ad_ = a_dst0 + (uint32_t)(buf) * 10240u; \
    CP16_CA(ad_,      as_); \
    CP16_CA(ad_ + 16, as_ + 4); \
    const float* bs_ = b_src0 + (size_t)(k0) * HWSZ; \
    uint32_t bd_ = b_dst0 + (uint32_t)(buf) * 8704u; \
    CP16_CG(bd_,      bs_); \
    CP16_CG(bd_ + 16, bs_ + 4); \
} while (0)

    P1_ISSUE(0, 0);  CP_COMMIT();
    P1_ISSUE(1, 16); CP_COMMIT();
    P1_ISSUE(2, 32); CP_COMMIT();

#pragma unroll 4
    for (int kt = 0; kt < 16; ++kt) {
        const int buf = kt & 3;
        CP_WAIT2();
        __syncthreads();
        if (kt + 3 < 16) P1_ISSUE((kt + 3) & 3, (kt + 3) * 16);
        CP_COMMIT();

#pragma unroll
        for (int ks = 0; ks < 16; ks += 8) {
            uint32_t af[4][4];
#pragma unroll
            for (int mt = 0; mt < 4; ++mt)
                ldsm_x4(af[mt][0], af[mt][1], af[mt][2], af[mt][3],
                        a_frag + (uint32_t)buf * 10240u + (uint32_t)mt * 1280u + (uint32_t)ks * 4u);
            uint32_t bf[4][2];
            const int kq = ks + kl;
#pragma unroll
            for (int nt = 0; nt < 4; ++nt) {
                int pc = warp_n * 32 + nt * 8 + q;
                bf[nt][0] = __float_as_uint(Bs[buf * 2176 + kq * 136 + pc]);
                bf[nt][1] = __float_as_uint(Bs[buf * 2176 + (kq + 4) * 136 + pc]);
            }
#pragma unroll
            for (int mt = 0; mt < 4; ++mt)
#pragma unroll
                for (int nt = 0; nt < 4; ++nt)
                    mma_tf32(acc[mt][nt], af[mt][0], af[mt][1], af[mt][2], af[mt][3],
                             bf[nt][0], bf[nt][1]);
        }
        __syncthreads();
    }
#undef P1_ISSUE

    float bias_v[4][2];
#pragma unroll
    for (int mt = 0; mt < 4; ++mt)
#pragma unroll
        for (int hi = 0; hi < 2; ++hi)
            bias_v[mt][hi] = bias[warp_m * 64 + mt * 16 + q + hi * 8];

    if (tid < 128) part[tid] = 0.f;

    // Epilogue: stage [px][64ch], coalesced stores + fused norm reduction
#pragma unroll
    for (int h = 0; h < 2; ++h) {
        __syncthreads();
        if (warp_m == h) {
#pragma unroll
            for (int mt = 0; mt < 4; ++mt)
#pragma unroll
                for (int nt = 0; nt < 4; ++nt)
#pragma unroll
                    for (int i = 0; i < 4; ++i) {
                        int px = warp_n * 32 + nt * 8 + 2 * kl + (i & 1);
                        int ch = mt * 16 + q + 8 * (i >> 1);
                        stage[px][ch] = acc[mt][nt][i] + bias_v[mt][i >> 1];
                    }
        }
        __syncthreads();
#pragma unroll
        for (int it = 0; it < 8; ++it) {
            int g = tid + it * 256;
            int px = g >> 4;
            int f  = g & 15;
            float4 v = *(float4*)&stage[px][f * 4];
            ((float4*)outp)[(size_t)(p0 + px) * 32 + h * 16 + f] = v;
            if (wsel < 2) {
                float sq = v.x * v.x + v.y * v.y + v.z * v.z + v.w * v.w;
                sq += __shfl_xor_sync(0xffffffffu, sq, 1);
                sq += __shfl_xor_sync(0xffffffffu, sq, 2);
                sq += __shfl_xor_sync(0xffffffffu, sq, 4);
                sq += __shfl_xor_sync(0xffffffffu, sq, 8);
                if (f == 0) part[px] += sq;   // same thread owns px across h: no race
            }
        }
    }
    __syncthreads();
    if (wsel < 2 && tid < 128) {
        float* np = (wsel == 0) ? g_tnorm : g_pnorm;
        np[p0 + tid] = sqrtf(part[tid]);
    }
}

// ---------------------------------------------------------------------------
// Pass 2 (smem-tiled, overlapped, NO spill): block = 32-px row strip.
// Phi and g neighborhoods issued as two cp.async groups up front (addresses
// recomputed inline, nothing cached in local); wait_group 1 releases phi
// while the g group streams behind the score computation.
// dyn smem: 2*13056 (tiles) + 320 (wt) + 104 (pnorm) = 26536 fl = 106144 B
// grid = P_TOT/32, block 256 (8 warps x 4 px each). 2 CTAs/SM.
// ---------------------------------------------------------------------------
__global__ __launch_bounds__(256) void pass2_attn()
{
    extern __shared__ __align__(16) float psm[];
    float* tphi = psm;                  // [102][128]
    float* tg   = psm + 13056;          // [102][128]
    float* wt_s = psm + 26112;          // [32][10]
    float* pn_s = psm + 26432;          // [102]

    const int tid  = threadIdx.x;
    const int warp = tid >> 5;
    const int lane = tid & 31;

    const int p0 = blockIdx.x * 32;
    const int b  = p0 / HWSZ;
    const int hw = p0 % HWSZ;
    const int h  = hw / WWID;
    const int w0 = hw % WWID;

    const float4* th4 = (const float4*)g_theta;
    const uint32_t phib = (uint32_t)__cvta_generic_to_shared(tphi);
    const uint32_t gb   = (uint32_t)__cvta_generic_to_shared(tg);

    // Group 1: phi neighborhood (addresses computed inline — no local array)
#pragma unroll 1
    for (int idx = tid; idx < 3264; idx += 256) {
        int pxl = idx >> 5;             // 0..101
        int f   = idx & 31;
        int r = pxl / 34, c = pxl % 34;
        int hr = min(max(h + r - 1, 0), HH - 1);
        int wc = min(max(w0 + c - 1, 0), WWID - 1);
        const float* src = g_phi + (((size_t)(b * HWSZ + hr * WWID + wc)) << 7) + f * 4;
        CP16_CG(phib + (uint32_t)idx * 16u, src);
    }
    CP_COMMIT();
    // Group 2: g neighborhood (lands while scores are computed)
#pragma unroll 1
    for (int idx = tid; idx < 3264; idx += 256) {
        int pxl = idx >> 5;
        int f   = idx & 31;
        int r = pxl / 34, c = pxl % 34;
        int hr = min(max(h + r - 1, 0), HH - 1);
        int wc = min(max(w0 + c - 1, 0), WWID - 1);
        const float* src = g_g + (((size_t)(b * HWSZ + hr * WWID + wc)) << 7) + f * 4;
        CP16_CG(gb + (uint32_t)idx * 16u, src);
    }
    CP_COMMIT();

    if (tid < 102) {
        int r = tid / 34, c = tid % 34;
        int hr = min(max(h + r - 1, 0), HH - 1);
        int wc = min(max(w0 + c - 1, 0), WWID - 1);
        pn_s[tid] = g_pnorm[b * HWSZ + hr * WWID + wc];
    }

    CP_WAIT1();          // phi ready; g group may still be in flight
    __syncthreads();

    // ---- scores + softmax per pixel (4 px per warp) ----
#pragma unroll
    for (int jj = 0; jj < 4; ++jj) {
        int pxl = warp * 4 + jj;        // 0..31
        int p = p0 + pxl;
        float4 th = th4[(size_t)p * 32 + lane];
        float tn = g_tnorm[p];

        float d[9];
#pragma unroll
        for (int n = 0; n < 9; ++n) {
            int di = n / 3, dj = n % 3;
            const float4 ph = *(const float4*)&tphi[((di * 34 + pxl + dj) * 32 + lane) * 4];
            d[n] = th.x * ph.x + th.y * ph.y + th.z * ph.z + th.w * ph.w;
        }
#pragma unroll
        for (int off = 16; off; off >>= 1)
#pragma unroll
            for (int n = 0; n < 9; ++n)
                d[n] += __shfl_xor_sync(0xffffffffu, d[n], off);

        float s = 0.f;
#pragma unroll
        for (int n = 0; n < 9; ++n) {
            int di = n / 3, dj = n % 3;
            float den = fmaxf(tn * pn_s[di * 34 + pxl + dj], 1e-8f);
            d[n] = __expf(d[n] / den);      // scores bounded in [-1,1]: no max-shift
            s += d[n];
        }
        float inv = 1.f / s;
        if (lane == 0) {
#pragma unroll
            for (int n = 0; n < 9; ++n) wt_s[pxl * 10 + n] = d[n] * inv;
        }
    }

    CP_WAIT0();          // g ready (mostly already landed)
    __syncthreads();

    // ---- weighted average ----
#pragma unroll
    for (int jj = 0; jj < 4; ++jj) {
        int pxl = warp * 4 + jj;
        int p = p0 + pxl;
        float wt[9];
#pragma unroll
        for (int n = 0; n < 9; ++n) wt[n] = wt_s[pxl * 10 + n];

        float4 acc = make_float4(0.f, 0.f, 0.f, 0.f);
#pragma unroll
        for (int n = 0; n < 9; ++n) {
            int di = n / 3, dj = n % 3;
            const float4 gv = *(const float4*)&tg[((di * 34 + pxl + dj) * 32 + lane) * 4];
            acc.x += wt[n] * gv.x; acc.y += wt[n] * gv.y;
            acc.z += wt[n] * gv.z; acc.w += wt[n] * gv.w;
        }
        uint4 o;
        o.x = f2tf32(acc.x); o.y = f2tf32(acc.y);
        o.z = f2tf32(acc.z); o.w = f2tf32(acc.w);
        ((uint4*)g_wa)[(size_t)p * 32 + lane] = o;
    }
}

// ---------------------------------------------------------------------------
// Pass 3 (tensor, 4-stage cp.async, R5 form): out = x + W_back@wa + b_back.
// Tile 128 ch x 128 px. dyn smem: 4*2560*2 = 20480 floats = 81920 B.
// grid = (576, 2)
// ---------------------------------------------------------------------------
__global__ __launch_bounds__(256, 2) void pass3_gemm(
    const float* __restrict__ x,
    const float* __restrict__ b_back,
    float* __restrict__ out)
{
    extern __shared__ __align__(16) float sm[];
    float* As = sm;                    // [4][128][20]
    float* Bs = sm + 4 * 2560;         // [4][128][20]
    float (*stage)[132] = (float(*)[132])sm;

    const int tid = threadIdx.x;
    const int lane = tid & 31;
    const int warp = tid >> 5;
    const int warp_m = warp >> 2;
    const int warp_n = warp & 3;
    const int q = lane >> 2;
    const int kl = lane & 3;

    const int p0 = blockIdx.x * 128;
    const int b = p0 / HWSZ;
    const int hw0 = p0 % HWSZ;
    const int c0 = blockIdx.y * 128;

    float acc[4][4][4];
#pragma unroll
    for (int mt = 0; mt < 4; ++mt)
#pragma unroll
        for (int nt = 0; nt < 4; ++nt)
#pragma unroll
            for (int i = 0; i < 4; ++i) acc[mt][nt][i] = 0.f;

    const int am   = tid >> 1;
    const int akq0 = (tid & 1) * 2;

    const uint32_t as_base = (uint32_t)__cvta_generic_to_shared(As);
    const uint32_t bs_base = (uint32_t)__cvta_generic_to_shared(Bs);
    const uint32_t a_dst0 = as_base + 4u * (uint32_t)(am * 20 + akq0 * 4);
    const uint32_t b_dst0 = bs_base + 4u * (uint32_t)(am * 20 + akq0 * 4);
    const float* a_src0 = g_wb + (size_t)(c0 + am) * C_O + akq0 * 4;
    const float* b_src0 = g_wa + (size_t)(p0 + am) * C_O + akq0 * 4;

    const uint32_t a_frag = as_base + 4u * ((uint32_t)(warp_m * 64 + (lane & 15)) * 20u
                                            + (uint32_t)(lane >> 4) * 4u);
    const uint32_t b_frag = bs_base + 4u * ((uint32_t)(warp_n * 32 + (lane & 7)) * 20u
                                            + (uint32_t)((lane >> 3) & 1) * 4u);

#define P3_ISSUE(buf, k0) do { \
    const float* as_ = a_src0 + (k0); \
    uint32_t ad_ = a_dst0 + (uint32_t)(buf) * 10240u; \
    CP16_CA(ad_,      as_); \
    CP16_CA(ad_ + 16, as_ + 4); \
    const float* bs_ = b_src0 + (k0); \
    uint32_t bd_ = b_dst0 + (uint32_t)(buf) * 10240u; \
    CP16_CG(bd_,      bs_); \
    CP16_CG(bd_ + 16, bs_ + 4); \
} while (0)

    P3_ISSUE(0, 0);  CP_COMMIT();
    P3_ISSUE(1, 16); CP_COMMIT();
    P3_ISSUE(2, 32); CP_COMMIT();

#pragma unroll 4
    for (int kt = 0; kt < 8; ++kt) {
        const int buf = kt & 3;
        CP_WAIT2();
        __syncthreads();
        if (kt + 3 < 8) P3_ISSUE((kt + 3) & 3, (kt + 3) * 16);
        CP_COMMIT();

#pragma unroll
        for (int ks = 0; ks < 16; ks += 8) {
            uint32_t af[4][4];
#pragma unroll
            for (int mt = 0; mt < 4; ++mt)
                ldsm_x4(af[mt][0], af[mt][1], af[mt][2], af[mt][3],
                        a_frag + (uint32_t)buf * 10240u + (uint32_t)mt * 1280u + (uint32_t)ks * 4u);
            uint32_t bf[4][2];
#pragma unroll
            for (int nt = 0; nt < 4; ++nt)
                ldsm_x2(bf[nt][0], bf[nt][1],
                        b_frag + (uint32_t)buf * 10240u + (uint32_t)nt * 640u + (uint32_t)ks * 4u);
#pragma unroll
            for (int mt = 0; mt < 4; ++mt)
#pragma unroll
                for (int nt = 0; nt < 4; ++nt)
                    mma_tf32(acc[mt][nt], af[mt][0], af[mt][1], af[mt][2], af[mt][3],
                             bf[nt][0], bf[nt][1]);
        }
        __syncthreads();
    }
#undef P3_ISSUE

    // Epilogue: stage [ch][px], then coalesced residual-add + store
#pragma unroll
    for (int h = 0; h < 2; ++h) {
        __syncthreads();
        if (warp_m == h) {
#pragma unroll
            for (int mt = 0; mt < 4; ++mt)
#pragma unroll
                for (int nt = 0; nt < 4; ++nt)
#pragma unroll
                    for (int hi = 0; hi < 2; ++hi) {
                        int ch = mt * 16 + q + 8 * hi;
                        int px = warp_n * 32 + nt * 8 + 2 * kl;
                        float2 v2 = make_float2(acc[mt][nt][hi * 2], acc[mt][nt][hi * 2 + 1]);
                        *(float2*)&stage[ch][px] = v2;
                    }
        }
        __syncthreads();
#pragma unroll
        for (int it = 0; it < 8; ++it) {
            int g = tid + it * 256;
            int ch = g >> 5;
            int f  = g & 31;
            int c  = c0 + h * 64 + ch;
            size_t gi = (((size_t)(b * C_IN + c)) * HWSZ + hw0) / 4 + f;
            float4 s = *(float4*)&stage[ch][f * 4];
            float4 xv = ((const float4*)x)[gi];
            float bb = b_back[c];
            float4 o4;
            o4.x = xv.x + bb + s.x;
            o4.y = xv.y + bb + s.y;
            o4.z = xv.z + bb + s.z;
            o4.w = xv.w + bb + s.w;
            ((float4*)out)[gi] = o4;
        }
    }
}

// ---------------------------------------------------------------------------
extern "C" void kernel_launch(void* const* d_in, const int* in_sizes, int n_in,
                              void* d_out, int out_size)
{
    const float* x       = (const float*)d_in[0];
    const float* w_theta = (const float*)d_in[1];
    const float* b_theta = (const float*)d_in[2];
    const float* w_phi   = (const float*)d_in[3];
    const float* b_phi   = (const float*)d_in[4];
    const float* w_g     = (const float*)d_in[5];
    const float* b_g     = (const float*)d_in[6];
    const float* w_back  = (const float*)d_in[7];
    const float* b_back  = (const float*)d_in[8];
    float* out = (float*)d_out;

    const int p1_smem = 19072 * 4;   // 76288 B
    const int p2_smem = 26536 * 4;   // 106144 B
    const int p3_smem = 20480 * 4;   // 81920 B
    cudaFuncSetAttribute(pass1_gemm, cudaFuncAttributeMaxDynamicSharedMemorySize, p1_smem);
    cudaFuncSetAttribute(pass2_attn, cudaFuncAttributeMaxDynamicSharedMemorySize, p2_smem);
    cudaFuncSetAttribute(pass3_gemm, cudaFuncAttributeMaxDynamicSharedMemorySize, p3_smem);

    cvt_weights<<<128, 256>>>(w_theta, w_phi, w_g, w_back);

    dim3 g1(3, P_TOT / 128, 1);
    pass1_gemm<<<g1, 256, p1_smem>>>(x, b_theta, b_phi, b_g);

    pass2_attn<<<P_TOT / 32, 256, p2_smem>>>();

    dim3 g3(P_TOT / 128, 2, 1);
    pass3_gemm<<<g3, 256, p3_smem>>>(x, b_back, out);
}

// round 12
// speedup vs baseline: 1.3022x; 1.0900x over previous
#include <cuda_runtime.h>
#include <math.h>
#include <stdint.h>

// Problem constants
#define HH 96
#define WWID 96
#define HWSZ (HH * WWID)          // 9216
#define BATCH 8
#define P_TOT (BATCH * HWSZ)      // 73728 pixels
#define C_IN 256
#define C_O 128

// Scratch (device globals — allocation-free per harness rules)
__device__ __align__(16) float g_theta[(size_t)P_TOT * C_O];
__device__ __align__(16) float g_phi  [(size_t)P_TOT * C_O];
__device__ __align__(16) float g_g    [(size_t)P_TOT * C_O];
__device__ __align__(16) float g_wa   [(size_t)P_TOT * C_O];   // stored tf32-rounded
__device__ __align__(16) float g_w3   [3 * C_O * C_IN];        // tf32 w_theta|w_phi|w_g
__device__ __align__(16) float g_wb   [C_IN * C_O];            // tf32 w_back
__device__ float g_tnorm[P_TOT];
__device__ float g_pnorm[P_TOT];

__device__ __forceinline__ uint32_t f2tf32(float x) {
    uint32_t r;
    asm("cvt.rna.tf32.f32 %0, %1;" : "=r"(r) : "f"(x));
    return r;
}

__device__ __forceinline__ void mma_tf32(float c[4],
                                         uint32_t a0, uint32_t a1, uint32_t a2, uint32_t a3,
                                         uint32_t b0, uint32_t b1) {
    asm volatile(
        "mma.sync.aligned.m16n8k8.row.col.f32.tf32.tf32.f32 "
        "{%0,%1,%2,%3},{%4,%5,%6,%7},{%8,%9},{%0,%1,%2,%3};"
        : "+f"(c[0]), "+f"(c[1]), "+f"(c[2]), "+f"(c[3])
        : "r"(a0), "r"(a1), "r"(a2), "r"(a3), "r"(b0), "r"(b1));
}

__device__ __forceinline__ void ldsm_x4(uint32_t& r0, uint32_t& r1, uint32_t& r2, uint32_t& r3,
                                        uint32_t addr) {
    asm volatile("ldmatrix.sync.aligned.m8n8.x4.shared.b16 {%0,%1,%2,%3}, [%4];"
                 : "=r"(r0), "=r"(r1), "=r"(r2), "=r"(r3) : "r"(addr));
}

__device__ __forceinline__ void ldsm_x2(uint32_t& r0, uint32_t& r1, uint32_t addr) {
    asm volatile("ldmatrix.sync.aligned.m8n8.x2.shared.b16 {%0,%1}, [%2];"
                 : "=r"(r0), "=r"(r1) : "r"(addr));
}

#define CP16_CA(dst, src) \
    asm volatile("cp.async.ca.shared.global [%0], [%1], 16;" :: "r"(dst), "l"(src))
#define CP16_CG(dst, src) \
    asm volatile("cp.async.cg.shared.global [%0], [%1], 16;" :: "r"(dst), "l"(src))
#define CP_COMMIT() asm volatile("cp.async.commit_group;")
#define CP_WAIT2()  asm volatile("cp.async.wait_group 2;")

// ---------------------------------------------------------------------------
// Setup: tf32-round all weights once.
// ---------------------------------------------------------------------------
__global__ void cvt_weights(const float* __restrict__ wt, const float* __restrict__ wp,
                            const float* __restrict__ wg, const float* __restrict__ wb)
{
    int i = blockIdx.x * 256 + threadIdx.x;      // 0 .. 32767
    g_w3[i]         = __uint_as_float(f2tf32(wt[i]));
    g_w3[32768 + i] = __uint_as_float(f2tf32(wp[i]));
    g_w3[65536 + i] = __uint_as_float(f2tf32(wg[i]));
    g_wb[i]         = __uint_as_float(f2tf32(wb[i]));
}

// ---------------------------------------------------------------------------
// Pass 1 (tensor, 4-stage cp.async): theta/phi/g = W(128x256)@x + bias.
// grid = (3, 576): wsel fastest -> 3 co-resident blocks share the x tile in L2.
// Norms of theta/phi computed in the epilogue.
// dyn smem: 4*(2560+2176) + 128 = 19072 floats = 76288 B.
// ---------------------------------------------------------------------------
__global__ __launch_bounds__(256, 2) void pass1_gemm(
    const float* __restrict__ x,
    const float* __restrict__ b_theta, const float* __restrict__ b_phi,
    const float* __restrict__ b_g)
{
    extern __shared__ __align__(16) float sm[];
    float* As = sm;                    // [4][128][20]
    float* Bs = sm + 4 * 2560;         // [4][16][136]
    float (*stage)[68] = (float(*)[68])sm;
    float* part = sm + 18944;          // [128] per-px sum of squares

    const int tid = threadIdx.x;
    const int lane = tid & 31;
    const int warp = tid >> 5;
    const int warp_m = warp >> 2;
    const int warp_n = warp & 3;
    const int q = lane >> 2;
    const int kl = lane & 3;

    const int wsel = blockIdx.x;
    const int p0 = blockIdx.y * 128;
    const int b = p0 / HWSZ;
    const int hw0 = p0 % HWSZ;

    const float* wsrc = g_w3 + wsel * 32768;
    const float* bias = (wsel == 0) ? b_theta : ((wsel == 1) ? b_phi : b_g);
    float* outp       = (wsel == 0) ? g_theta : ((wsel == 1) ? g_phi : g_g);

    float acc[4][4][4];
#pragma unroll
    for (int mt = 0; mt < 4; ++mt)
#pragma unroll
        for (int nt = 0; nt < 4; ++nt)
#pragma unroll
            for (int i = 0; i < 4; ++i) acc[mt][nt][i] = 0.f;

    const int am   = tid >> 1;
    const int akq0 = (tid & 1) * 2;
    const int bk   = tid >> 4;
    const int bpq0 = (tid & 15) * 2;

    const uint32_t as_base = (uint32_t)__cvta_generic_to_shared(As);
    const uint32_t bs_base = (uint32_t)__cvta_generic_to_shared(Bs);
    const uint32_t a_dst0 = as_base + 4u * (uint32_t)(am * 20 + akq0 * 4);
    const uint32_t b_dst0 = bs_base + 4u * (uint32_t)(bk * 136 + bpq0 * 4);
    const float* a_src0 = wsrc + am * C_IN + akq0 * 4;
    const float* b_src0 = x + (size_t)(b * C_IN + bk) * HWSZ + hw0 + bpq0 * 4;

    const uint32_t a_frag = as_base + 4u * ((uint32_t)(warp_m * 64 + (lane & 15)) * 20u
                                            + (uint32_t)(lane >> 4) * 4u);

#define P1_ISSUE(buf, k0) do { \
    const float* as_ = a_src0 + (k0); \
    uint32_t ad_ = a_dst0 + (uint32_t)(buf) * 10240u; \
    CP16_CA(ad_,      as_); \
    CP16_CA(ad_ + 16, as_ + 4); \
    const float* bs_ = b_src0 + (size_t)(k0) * HWSZ; \
    uint32_t bd_ = b_dst0 + (uint32_t)(buf) * 8704u; \
    CP16_CG(bd_,      bs_); \
    CP16_CG(bd_ + 16, bs_ + 4); \
} while (0)

    P1_ISSUE(0, 0);  CP_COMMIT();
    P1_ISSUE(1, 16); CP_COMMIT();
    P1_ISSUE(2, 32); CP_COMMIT();

#pragma unroll 4
    for (int kt = 0; kt < 16; ++kt) {
        const int buf = kt & 3;
        CP_WAIT2();
        __syncthreads();
        if (kt + 3 < 16) P1_ISSUE((kt + 3) & 3, (kt + 3) * 16);
        CP_COMMIT();

#pragma unroll
        for (int ks = 0; ks < 16; ks += 8) {
            uint32_t af[4][4];
#pragma unroll
            for (int mt = 0; mt < 4; ++mt)
                ldsm_x4(af[mt][0], af[mt][1], af[mt][2], af[mt][3],
                        a_frag + (uint32_t)buf * 10240u + (uint32_t)mt * 1280u + (uint32_t)ks * 4u);
            uint32_t bf[4][2];
            const int kq = ks + kl;
#pragma unroll
            for (int nt = 0; nt < 4; ++nt) {
                int pc = warp_n * 32 + nt * 8 + q;
                bf[nt][0] = __float_as_uint(Bs[buf * 2176 + kq * 136 + pc]);
                bf[nt][1] = __float_as_uint(Bs[buf * 2176 + (kq + 4) * 136 + pc]);
            }
#pragma unroll
            for (int mt = 0; mt < 4; ++mt)
#pragma unroll
                for (int nt = 0; nt < 4; ++nt)
                    mma_tf32(acc[mt][nt], af[mt][0], af[mt][1], af[mt][2], af[mt][3],
                             bf[nt][0], bf[nt][1]);
        }
        __syncthreads();
    }
#undef P1_ISSUE

    float bias_v[4][2];
#pragma unroll
    for (int mt = 0; mt < 4; ++mt)
#pragma unroll
        for (int hi = 0; hi < 2; ++hi)
            bias_v[mt][hi] = bias[warp_m * 64 + mt * 16 + q + hi * 8];

    if (tid < 128) part[tid] = 0.f;

    // Epilogue: stage [px][64ch], coalesced stores + fused norm reduction
#pragma unroll
    for (int h = 0; h < 2; ++h) {
        __syncthreads();
        if (warp_m == h) {
#pragma unroll
            for (int mt = 0; mt < 4; ++mt)
#pragma unroll
                for (int nt = 0; nt < 4; ++nt)
#pragma unroll
                    for (int i = 0; i < 4; ++i) {
                        int px = warp_n * 32 + nt * 8 + 2 * kl + (i & 1);
                        int ch = mt * 16 + q + 8 * (i >> 1);
                        stage[px][ch] = acc[mt][nt][i] + bias_v[mt][i >> 1];
                    }
        }
        __syncthreads();
#pragma unroll
        for (int it = 0; it < 8; ++it) {
            int g = tid + it * 256;
            int px = g >> 4;
            int f  = g & 15;
            float4 v = *(float4*)&stage[px][f * 4];
            ((float4*)outp)[(size_t)(p0 + px) * 32 + h * 16 + f] = v;
            if (wsel < 2) {
                float sq = v.x * v.x + v.y * v.y + v.z * v.z + v.w * v.w;
                sq += __shfl_xor_sync(0xffffffffu, sq, 1);
                sq += __shfl_xor_sync(0xffffffffu, sq, 2);
                sq += __shfl_xor_sync(0xffffffffu, sq, 4);
                sq += __shfl_xor_sync(0xffffffffu, sq, 8);
                if (f == 0) part[px] += sq;   // same thread owns px across h: no race
            }
        }
    }
    __syncthreads();
    if (wsel < 2 && tid < 128) {
        float* np = (wsel == 0) ? g_tnorm : g_pnorm;
        np[p0 + tid] = sqrtf(part[tid]);
    }
}

// ---------------------------------------------------------------------------
// Pass 2: 2 adjacent pixels per warp; 3x4 neighborhood shared (12 loads of
// phi/g instead of 18). All arrays compile-time indexed -> registers.
// grid = P_TOT/16, block 256 (8 warps x 2 px each).
// ---------------------------------------------------------------------------
__global__ __launch_bounds__(256) void pass2_attn()
{
    const int warp = threadIdx.x >> 5;
    const int lane = threadIdx.x & 31;
    const int p0 = (blockIdx.x * 8 + warp) * 2;
    const int b  = p0 / HWSZ;
    const int hw = p0 % HWSZ;
    const int h  = hw / WWID;
    const int w  = hw % WWID;          // even; pair stays within one row

    const float4* th4 = (const float4*)g_theta;
    const float4* ph4 = (const float4*)g_phi;
    const float4* gg4 = (const float4*)g_g;

    float4 th0 = th4[(size_t)p0 * 32 + lane];
    float4 th1 = th4[(size_t)(p0 + 1) * 32 + lane];
    float tn0 = g_tnorm[p0];
    float tn1 = g_tnorm[p0 + 1];

    // 3x4 neighborhood positions (constant-indexed arrays -> registers)
    int np[12];
    float pnv[12];
#pragma unroll
    for (int r = 0; r < 3; ++r) {
        int hr = min(max(h + r - 1, 0), HH - 1);
        int rowb = b * HWSZ + hr * WWID;
#pragma unroll
        for (int c = 0; c < 4; ++c) {
            int wc = min(max(w + c - 1, 0), WWID - 1);
            np[r * 4 + c] = rowb + wc;
            pnv[r * 4 + c] = g_pnorm[rowb + wc];
        }
    }

    // partial dots: pixel 0 uses cols 0..2, pixel 1 uses cols 1..3
    float d0[9], d1[9];
#pragma unroll
    for (int r = 0; r < 3; ++r)
#pragma unroll
        for (int c = 0; c < 4; ++c) {
            float4 ph = ph4[(size_t)np[r * 4 + c] * 32 + lane];
            if (c <= 2)
                d0[r * 3 + c] = th0.x * ph.x + th0.y * ph.y + th0.z * ph.z + th0.w * ph.w;
            if (c >= 1)
                d1[r * 3 + c - 1] = th1.x * ph.x + th1.y * ph.y + th1.z * ph.z + th1.w * ph.w;
        }

    // 18 independent butterfly chains
#pragma unroll
    for (int off = 16; off; off >>= 1)
#pragma unroll
        for (int n = 0; n < 9; ++n) {
            d0[n] += __shfl_xor_sync(0xffffffffu, d0[n], off);
            d1[n] += __shfl_xor_sync(0xffffffffu, d1[n], off);
        }

    // scores + softmax (bounded in [-1,1]: no max-shift needed)
    float s0 = 0.f, s1 = 0.f;
#pragma unroll
    for (int n = 0; n < 9; ++n) {
        int r = n / 3, c = n % 3;
        d0[n] = __expf(d0[n] / fmaxf(tn0 * pnv[r * 4 + c], 1e-8f));
        s0 += d0[n];
        d1[n] = __expf(d1[n] / fmaxf(tn1 * pnv[r * 4 + c + 1], 1e-8f));
        s1 += d1[n];
    }
    float i0 = 1.f / s0, i1 = 1.f / s1;

    // weighted average of g (12 loads serve both pixels)
    float4 a0 = make_float4(0.f, 0.f, 0.f, 0.f);
    float4 a1 = make_float4(0.f, 0.f, 0.f, 0.f);
#pragma unroll
    for (int r = 0; r < 3; ++r)
#pragma unroll
        for (int c = 0; c < 4; ++c) {
            float4 gv = gg4[(size_t)np[r * 4 + c] * 32 + lane];
            if (c <= 2) {
                float a = d0[r * 3 + c] * i0;
                a0.x += a * gv.x; a0.y += a * gv.y;
                a0.z += a * gv.z; a0.w += a * gv.w;
            }
            if (c >= 1) {
                float a = d1[r * 3 + c - 1] * i1;
                a1.x += a * gv.x; a1.y += a * gv.y;
                a1.z += a * gv.z; a1.w += a * gv.w;
            }
        }

    uint4 o0, o1;
    o0.x = f2tf32(a0.x); o0.y = f2tf32(a0.y); o0.z = f2tf32(a0.z); o0.w = f2tf32(a0.w);
    o1.x = f2tf32(a1.x); o1.y = f2tf32(a1.y); o1.z = f2tf32(a1.z); o1.w = f2tf32(a1.w);
    ((uint4*)g_wa)[(size_t)p0 * 32 + lane] = o0;
    ((uint4*)g_wa)[(size_t)(p0 + 1) * 32 + lane] = o1;
}

// ---------------------------------------------------------------------------
// Pass 3 (tensor, 4-stage cp.async, R5 form): out = x + W_back@wa + b_back.
// Tile 128 ch x 128 px. dyn smem: 4*2560*2 = 20480 floats = 81920 B.
// grid = (576, 2)
// ---------------------------------------------------------------------------
__global__ __launch_bounds__(256, 2) void pass3_gemm(
    const float* __restrict__ x,
    const float* __restrict__ b_back,
    float* __restrict__ out)
{
    extern __shared__ __align__(16) float sm[];
    float* As = sm;                    // [4][128][20]
    float* Bs = sm + 4 * 2560;         // [4][128][20]
    float (*stage)[132] = (float(*)[132])sm;

    const int tid = threadIdx.x;
    const int lane = tid & 31;
    const int warp = tid >> 5;
    const int warp_m = warp >> 2;
    const int warp_n = warp & 3;
    const int q = lane >> 2;
    const int kl = lane & 3;

    const int p0 = blockIdx.x * 128;
    const int b = p0 / HWSZ;
    const int hw0 = p0 % HWSZ;
    const int c0 = blockIdx.y * 128;

    float acc[4][4][4];
#pragma unroll
    for (int mt = 0; mt < 4; ++mt)
#pragma unroll
        for (int nt = 0; nt < 4; ++nt)
#pragma unroll
            for (int i = 0; i < 4; ++i) acc[mt][nt][i] = 0.f;

    const int am   = tid >> 1;
    const int akq0 = (tid & 1) * 2;

    const uint32_t as_base = (uint32_t)__cvta_generic_to_shared(As);
    const uint32_t bs_base = (uint32_t)__cvta_generic_to_shared(Bs);
    const uint32_t a_dst0 = as_base + 4u * (uint32_t)(am * 20 + akq0 * 4);
    const uint32_t b_dst0 = bs_base + 4u * (uint32_t)(am * 20 + akq0 * 4);
    const float* a_src0 = g_wb + (size_t)(c0 + am) * C_O + akq0 * 4;
    const float* b_src0 = g_wa + (size_t)(p0 + am) * C_O + akq0 * 4;

    const uint32_t a_frag = as_base + 4u * ((uint32_t)(warp_m * 64 + (lane & 15)) * 20u
                                            + (uint32_t)(lane >> 4) * 4u);
    const uint32_t b_frag = bs_base + 4u * ((uint32_t)(warp_n * 32 + (lane & 7)) * 20u
                                            + (uint32_t)((lane >> 3) & 1) * 4u);

#define P3_ISSUE(buf, k0) do { \
    const float* as_ = a_src0 + (k0); \
    uint32_t ad_ = a_dst0 + (uint32_t)(buf) * 10240u; \
    CP16_CA(ad_,      as_); \
    CP16_CA(ad_ + 16, as_ + 4); \
    const float* bs_ = b_src0 + (k0); \
    uint32_t bd_ = b_dst0 + (uint32_t)(buf) * 10240u; \
    CP16_CG(bd_,      bs_); \
    CP16_CG(bd_ + 16, bs_ + 4); \
} while (0)

    P3_ISSUE(0, 0);  CP_COMMIT();
    P3_ISSUE(1, 16); CP_COMMIT();
    P3_ISSUE(2, 32); CP_COMMIT();

#pragma unroll 4
    for (int kt = 0; kt < 8; ++kt) {
        const int buf = kt & 3;
        CP_WAIT2();
        __syncthreads();
        if (kt + 3 < 8) P3_ISSUE((kt + 3) & 3, (kt + 3) * 16);
        CP_COMMIT();

#pragma unroll
        for (int ks = 0; ks < 16; ks += 8) {
            uint32_t af[4][4];
#pragma unroll
            for (int mt = 0; mt < 4; ++mt)
                ldsm_x4(af[mt][0], af[mt][1], af[mt][2], af[mt][3],
                        a_frag + (uint32_t)buf * 10240u + (uint32_t)mt * 1280u + (uint32_t)ks * 4u);
            uint32_t bf[4][2];
#pragma unroll
            for (int nt = 0; nt < 4; ++nt)
                ldsm_x2(bf[nt][0], bf[nt][1],
                        b_frag + (uint32_t)buf * 10240u + (uint32_t)nt * 640u + (uint32_t)ks * 4u);
#pragma unroll
            for (int mt = 0; mt < 4; ++mt)
#pragma unroll
                for (int nt = 0; nt < 4; ++nt)
                    mma_tf32(acc[mt][nt], af[mt][0], af[mt][1], af[mt][2], af[mt][3],
                             bf[nt][0], bf[nt][1]);
        }
        __syncthreads();
    }
#undef P3_ISSUE

    // Epilogue: stage [ch][px], then coalesced residual-add + store
#pragma unroll
    for (int h = 0; h < 2; ++h) {
        __syncthreads();
        if (warp_m == h) {
#pragma unroll
            for (int mt = 0; mt < 4; ++mt)
#pragma unroll
                for (int nt = 0; nt < 4; ++nt)
#pragma unroll
                    for (int hi = 0; hi < 2; ++hi) {
                        int ch = mt * 16 + q + 8 * hi;
                        int px = warp_n * 32 + nt * 8 + 2 * kl;
                        float2 v2 = make_float2(acc[mt][nt][hi * 2], acc[mt][nt][hi * 2 + 1]);
                        *(float2*)&stage[ch][px] = v2;
                    }
        }
        __syncthreads();
#pragma unroll
        for (int it = 0; it < 8; ++it) {
            int g = tid + it * 256;
            int ch = g >> 5;
            int f  = g & 31;
            int c  = c0 + h * 64 + ch;
            size_t gi = (((size_t)(b * C_IN + c)) * HWSZ + hw0) / 4 + f;
            float4 s = *(float4*)&stage[ch][f * 4];
            float4 xv = ((const float4*)x)[gi];
            float bb = b_back[c];
            float4 o4;
            o4.x = xv.x + bb + s.x;
            o4.y = xv.y + bb + s.y;
            o4.z = xv.z + bb + s.z;
            o4.w = xv.w + bb + s.w;
            ((float4*)out)[gi] = o4;
        }
    }
}

// ---------------------------------------------------------------------------
extern "C" void kernel_launch(void* const* d_in, const int* in_sizes, int n_in,
                              void* d_out, int out_size)
{
    const float* x       = (const float*)d_in[0];
    const float* w_theta = (const float*)d_in[1];
    const float* b_theta = (const float*)d_in[2];
    const float* w_phi   = (const float*)d_in[3];
    const float* b_phi   = (const float*)d_in[4];
    const float* w_g     = (const float*)d_in[5];
    const float* b_g     = (const float*)d_in[6];
    const float* w_back  = (const float*)d_in[7];
    const float* b_back  = (const float*)d_in[8];
    float* out = (float*)d_out;

    const int p1_smem = 19072 * 4;   // 76288 B
    const int p3_smem = 20480 * 4;   // 81920 B
    cudaFuncSetAttribute(pass1_gemm, cudaFuncAttributeMaxDynamicSharedMemorySize, p1_smem);
    cudaFuncSetAttribute(pass3_gemm, cudaFuncAttributeMaxDynamicSharedMemorySize, p3_smem);

    cvt_weights<<<128, 256>>>(w_theta, w_phi, w_g, w_back);

    dim3 g1(3, P_TOT / 128, 1);
    pass1_gemm<<<g1, 256, p1_smem>>>(x, b_theta, b_phi, b_g);

    pass2_attn<<<P_TOT / 16, 256>>>();

    dim3 g3(P_TOT / 128, 2, 1);
    pass3_gemm<<<g3, 256, p3_smem>>>(x, b_back, out);
}

// round 13
// speedup vs baseline: 1.6396x; 1.2591x over previous
#include <cuda_runtime.h>
#include <cuda_bf16.h>
#include <math.h>
#include <stdint.h>

// Problem constants
#define HH 96
#define WWID 96
#define HWSZ (HH * WWID)          // 9216
#define BATCH 8
#define P_TOT (BATCH * HWSZ)      // 73728 pixels
#define C_IN 256
#define C_O 128

// Scratch (device globals — allocation-free per harness rules)
__device__ __align__(16) float g_theta[(size_t)P_TOT * C_O];
__device__ __align__(16) float g_phi  [(size_t)P_TOT * C_O];
__device__ __align__(16) float g_g    [(size_t)P_TOT * C_O];
__device__ __align__(16) __nv_bfloat16 g_wab[(size_t)P_TOT * C_O];       // wa, bf16
__device__ __align__(16) __nv_bfloat16 g_xb [(size_t)BATCH * C_IN * HWSZ]; // x, bf16
__device__ __align__(16) __nv_bfloat16 g_w3b[3 * C_O * C_IN];            // bf16 weights
__device__ __align__(16) __nv_bfloat16 g_wbb[C_IN * C_O];                // bf16 w_back
__device__ float g_tnorm[P_TOT];
__device__ float g_pnorm[P_TOT];

__device__ __forceinline__ uint32_t pack_bf16(float lo, float hi) {
    uint32_t r;
    asm("cvt.rn.bf16x2.f32 %0, %1, %2;" : "=r"(r) : "f"(hi), "f"(lo));
    return r;
}

__device__ __forceinline__ void mma_bf16(float c[4],
                                         uint32_t a0, uint32_t a1, uint32_t a2, uint32_t a3,
                                         uint32_t b0, uint32_t b1) {
    asm volatile(
        "mma.sync.aligned.m16n8k16.row.col.f32.bf16.bf16.f32 "
        "{%0,%1,%2,%3},{%4,%5,%6,%7},{%8,%9},{%0,%1,%2,%3};"
        : "+f"(c[0]), "+f"(c[1]), "+f"(c[2]), "+f"(c[3])
        : "r"(a0), "r"(a1), "r"(a2), "r"(a3), "r"(b0), "r"(b1));
}

__device__ __forceinline__ void ldsm_x4(uint32_t& r0, uint32_t& r1, uint32_t& r2, uint32_t& r3,
                                        uint32_t addr) {
    asm volatile("ldmatrix.sync.aligned.m8n8.x4.shared.b16 {%0,%1,%2,%3}, [%4];"
                 : "=r"(r0), "=r"(r1), "=r"(r2), "=r"(r3) : "r"(addr));
}

__device__ __forceinline__ void ldsm_x2(uint32_t& r0, uint32_t& r1, uint32_t addr) {
    asm volatile("ldmatrix.sync.aligned.m8n8.x2.shared.b16 {%0,%1}, [%2];"
                 : "=r"(r0), "=r"(r1) : "r"(addr));
}

__device__ __forceinline__ void ldsm_x2_tr(uint32_t& r0, uint32_t& r1, uint32_t addr) {
    asm volatile("ldmatrix.sync.aligned.m8n8.x2.trans.shared.b16 {%0,%1}, [%2];"
                 : "=r"(r0), "=r"(r1) : "r"(addr));
}

#define CP16_CA(dst, src) \
    asm volatile("cp.async.ca.shared.global [%0], [%1], 16;" :: "r"(dst), "l"(src))
#define CP16_CG(dst, src) \
    asm volatile("cp.async.cg.shared.global [%0], [%1], 16;" :: "r"(dst), "l"(src))
#define CP_COMMIT() asm volatile("cp.async.commit_group;")
#define CP_WAIT2()  asm volatile("cp.async.wait_group 2;")

// ---------------------------------------------------------------------------
// Setup: bf16-convert weights (once) and x (once).
// ---------------------------------------------------------------------------
__global__ void cvt_weights(const float* __restrict__ wt, const float* __restrict__ wp,
                            const float* __restrict__ wg, const float* __restrict__ wb)
{
    int i = blockIdx.x * 256 + threadIdx.x;      // 0 .. 32767
    g_w3b[i]         = __float2bfloat16(wt[i]);
    g_w3b[32768 + i] = __float2bfloat16(wp[i]);
    g_w3b[65536 + i] = __float2bfloat16(wg[i]);
    g_wbb[i]         = __float2bfloat16(wb[i]);
}

__global__ void cvt_x(const float4* __restrict__ x4)
{
    size_t i = (size_t)blockIdx.x * 256 + threadIdx.x;   // 0 .. 4718591
    float4 v = x4[i];
    uint2 o;
    o.x = pack_bf16(v.x, v.y);
    o.y = pack_bf16(v.z, v.w);
    ((uint2*)g_xb)[i] = o;
}

// ---------------------------------------------------------------------------
// Pass 1 (bf16 tensor, 4-stage cp.async): theta/phi/g = W(128x256)@x + bias.
// k-tile 32 (2 x k16 MMA steps), 8 k-iterations. grid = (3, 576).
// A smem [128 m][40 bf16] (80B rows), B smem [32 k][136 bf16] (272B rows).
// Per-stage: A 10240B + B 8704B. dyn smem: 4*18944 + 512 = 76288 B.
// ---------------------------------------------------------------------------
__global__ __launch_bounds__(256, 2) void pass1_gemm(
    const float* __restrict__ b_theta, const float* __restrict__ b_phi,
    const float* __restrict__ b_g)
{
    extern __shared__ __align__(16) float sm[];
    float (*stage)[68] = (float(*)[68])sm;
    float* part = sm + 18944;          // [128] per-px sum of squares

    const int tid = threadIdx.x;
    const int lane = tid & 31;
    const int warp = tid >> 5;
    const int warp_m = warp >> 2;
    const int warp_n = warp & 3;
    const int q = lane >> 2;
    const int kl = lane & 3;

    const int wsel = blockIdx.x;
    const int p0 = blockIdx.y * 128;
    const int b = p0 / HWSZ;
    const int hw0 = p0 % HWSZ;

    const __nv_bfloat16* wsrc = g_w3b + wsel * 32768;
    const float* bias = (wsel == 0) ? b_theta : ((wsel == 1) ? b_phi : b_g);
    float* outp       = (wsel == 0) ? g_theta : ((wsel == 1) ? g_phi : g_g);

    float acc[4][4][4];
#pragma unroll
    for (int mt = 0; mt < 4; ++mt)
#pragma unroll
        for (int nt = 0; nt < 4; ++nt)
#pragma unroll
            for (int i = 0; i < 4; ++i) acc[mt][nt][i] = 0.f;

    // loaders
    const int am = tid >> 1;           // A row m (0..127)
    const int ah = tid & 1;            // A 32B-half within 64B row
    const int brow = tid >> 4;         // B k row (0..15; +16 for 2nd chunk)
    const int bcol = tid & 15;         // B 16B chunk along 128 px

    const uint32_t as_base = (uint32_t)__cvta_generic_to_shared(sm);
    const uint32_t bs_base = as_base + 40960u;           // 4 A stages
    const uint32_t a_dst0 = as_base + (uint32_t)(am * 80 + ah * 32);
    const uint32_t b_dst0 = bs_base + (uint32_t)(brow * 272 + bcol * 16);
    const __nv_bfloat16* a_src0 = wsrc + am * C_IN + ah * 16;
    const __nv_bfloat16* b_src0 = g_xb + (size_t)(b * C_IN + brow) * HWSZ + hw0 + bcol * 8;

    const uint32_t a_frag = as_base + (uint32_t)((warp_m * 64 + (lane & 15)) * 80
                                                 + (lane >> 4) * 16);
    const uint32_t b_frag = bs_base + (uint32_t)((lane & 15) * 272 + warp_n * 64);

#define P1_ISSUE(buf, k0) do { \
    const __nv_bfloat16* as_ = a_src0 + (k0); \
    uint32_t ad_ = a_dst0 + (uint32_t)(buf) * 10240u; \
    CP16_CA(ad_,      as_); \
    CP16_CA(ad_ + 16, as_ + 8); \
    const __nv_bfloat16* bs_ = b_src0 + (size_t)(k0) * HWSZ; \
    uint32_t bd_ = b_dst0 + (uint32_t)(buf) * 8704u; \
    CP16_CG(bd_,        bs_); \
    CP16_CG(bd_ + 4352, bs_ + 16 * HWSZ); \
} while (0)

    P1_ISSUE(0, 0);  CP_COMMIT();
    P1_ISSUE(1, 32); CP_COMMIT();
    P1_ISSUE(2, 64); CP_COMMIT();

#pragma unroll 4
    for (int kt = 0; kt < 8; ++kt) {
        const int buf = kt & 3;
        CP_WAIT2();
        __syncthreads();
        if (kt + 3 < 8) P1_ISSUE((kt + 3) & 3, (kt + 3) * 32);
        CP_COMMIT();

#pragma unroll
        for (int ks = 0; ks < 2; ++ks) {
            uint32_t af[4][4];
#pragma unroll
            for (int mt = 0; mt < 4; ++mt)
                ldsm_x4(af[mt][0], af[mt][1], af[mt][2], af[mt][3],
                        a_frag + (uint32_t)buf * 10240u + (uint32_t)mt * 1280u
                               + (uint32_t)ks * 32u);
            uint32_t bf[4][2];
#pragma unroll
            for (int nt = 0; nt < 4; ++nt)
                ldsm_x2_tr(bf[nt][0], bf[nt][1],
                           b_frag + (uint32_t)buf * 8704u + (uint32_t)ks * 4352u
                                  + (uint32_t)nt * 16u);
#pragma unroll
            for (int mt = 0; mt < 4; ++mt)
#pragma unroll
                for (int nt = 0; nt < 4; ++nt)
                    mma_bf16(acc[mt][nt], af[mt][0], af[mt][1], af[mt][2], af[mt][3],
                             bf[nt][0], bf[nt][1]);
        }
        __syncthreads();
    }
#undef P1_ISSUE

    float bias_v[4][2];
#pragma unroll
    for (int mt = 0; mt < 4; ++mt)
#pragma unroll
        for (int hi = 0; hi < 2; ++hi)
            bias_v[mt][hi] = bias[warp_m * 64 + mt * 16 + q + hi * 8];

    if (tid < 128) part[tid] = 0.f;

    // Epilogue: stage [px][64ch], coalesced fp32 stores + fused norm reduction
#pragma unroll
    for (int h = 0; h < 2; ++h) {
        __syncthreads();
        if (warp_m == h) {
#pragma unroll
            for (int mt = 0; mt < 4; ++mt)
#pragma unroll
                for (int nt = 0; nt < 4; ++nt)
#pragma unroll
                    for (int i = 0; i < 4; ++i) {
                        int px = warp_n * 32 + nt * 8 + 2 * kl + (i & 1);
                        int ch = mt * 16 + q + 8 * (i >> 1);
                        stage[px][ch] = acc[mt][nt][i] + bias_v[mt][i >> 1];
                    }
        }
        __syncthreads();
#pragma unroll
        for (int it = 0; it < 8; ++it) {
            int g = tid + it * 256;
            int px = g >> 4;
            int f  = g & 15;
            float4 v = *(float4*)&stage[px][f * 4];
            ((float4*)outp)[(size_t)(p0 + px) * 32 + h * 16 + f] = v;
            if (wsel < 2) {
                float sq = v.x * v.x + v.y * v.y + v.z * v.z + v.w * v.w;
                sq += __shfl_xor_sync(0xffffffffu, sq, 1);
                sq += __shfl_xor_sync(0xffffffffu, sq, 2);
                sq += __shfl_xor_sync(0xffffffffu, sq, 4);
                sq += __shfl_xor_sync(0xffffffffu, sq, 8);
                if (f == 0) part[px] += sq;   // same thread owns px across h: no race
            }
        }
    }
    __syncthreads();
    if (wsel < 2 && tid < 128) {
        float* np = (wsel == 0) ? g_tnorm : g_pnorm;
        np[p0 + tid] = sqrtf(part[tid]);
    }
}

// ---------------------------------------------------------------------------
// Pass 2: 2 adjacent pixels per warp; 3x4 neighborhood shared (R12 form).
// wa written as bf16 for pass3. grid = P_TOT/16, block 256.
// ---------------------------------------------------------------------------
__global__ __launch_bounds__(256) void pass2_attn()
{
    const int warp = threadIdx.x >> 5;
    const int lane = threadIdx.x & 31;
    const int p0 = (blockIdx.x * 8 + warp) * 2;
    const int b  = p0 / HWSZ;
    const int hw = p0 % HWSZ;
    const int h  = hw / WWID;
    const int w  = hw % WWID;          // even; pair stays within one row

    const float4* th4 = (const float4*)g_theta;
    const float4* ph4 = (const float4*)g_phi;
    const float4* gg4 = (const float4*)g_g;

    float4 th0 = th4[(size_t)p0 * 32 + lane];
    float4 th1 = th4[(size_t)(p0 + 1) * 32 + lane];
    float tn0 = g_tnorm[p0];
    float tn1 = g_tnorm[p0 + 1];

    int np[12];
    float pnv[12];
#pragma unroll
    for (int r = 0; r < 3; ++r) {
        int hr = min(max(h + r - 1, 0), HH - 1);
        int rowb = b * HWSZ + hr * WWID;
#pragma unroll
        for (int c = 0; c < 4; ++c) {
            int wc = min(max(w + c - 1, 0), WWID - 1);
            np[r * 4 + c] = rowb + wc;
            pnv[r * 4 + c] = g_pnorm[rowb + wc];
        }
    }

    float d0[9], d1[9];
#pragma unroll
    for (int r = 0; r < 3; ++r)
#pragma unroll
        for (int c = 0; c < 4; ++c) {
            float4 ph = ph4[(size_t)np[r * 4 + c] * 32 + lane];
            if (c <= 2)
                d0[r * 3 + c] = th0.x * ph.x + th0.y * ph.y + th0.z * ph.z + th0.w * ph.w;
            if (c >= 1)
                d1[r * 3 + c - 1] = th1.x * ph.x + th1.y * ph.y + th1.z * ph.z + th1.w * ph.w;
        }

#pragma unroll
    for (int off = 16; off; off >>= 1)
#pragma unroll
        for (int n = 0; n < 9; ++n) {
            d0[n] += __shfl_xor_sync(0xffffffffu, d0[n], off);
            d1[n] += __shfl_xor_sync(0xffffffffu, d1[n], off);
        }

    float s0 = 0.f, s1 = 0.f;
#pragma unroll
    for (int n = 0; n < 9; ++n) {
        int r = n / 3, c = n % 3;
        d0[n] = __expf(d0[n] / fmaxf(tn0 * pnv[r * 4 + c], 1e-8f));
        s0 += d0[n];
        d1[n] = __expf(d1[n] / fmaxf(tn1 * pnv[r * 4 + c + 1], 1e-8f));
        s1 += d1[n];
    }
    float i0 = 1.f / s0, i1 = 1.f / s1;

    float4 a0 = make_float4(0.f, 0.f, 0.f, 0.f);
    float4 a1 = make_float4(0.f, 0.f, 0.f, 0.f);
#pragma unroll
    for (int r = 0; r < 3; ++r)
#pragma unroll
        for (int c = 0; c < 4; ++c) {
            float4 gv = gg4[(size_t)np[r * 4 + c] * 32 + lane];
            if (c <= 2) {
                float a = d0[r * 3 + c] * i0;
                a0.x += a * gv.x; a0.y += a * gv.y;
                a0.z += a * gv.z; a0.w += a * gv.w;
            }
            if (c >= 1) {
                float a = d1[r * 3 + c - 1] * i1;
                a1.x += a * gv.x; a1.y += a * gv.y;
                a1.z += a * gv.z; a1.w += a * gv.w;
            }
        }

    uint2 o0, o1;
    o0.x = pack_bf16(a0.x, a0.y); o0.y = pack_bf16(a0.z, a0.w);
    o1.x = pack_bf16(a1.x, a1.y); o1.y = pack_bf16(a1.z, a1.w);
    ((uint2*)g_wab)[(size_t)p0 * 32 + lane] = o0;
    ((uint2*)g_wab)[(size_t)(p0 + 1) * 32 + lane] = o1;
}

// ---------------------------------------------------------------------------
// Pass 3 (bf16 tensor, 4-stage cp.async): out = x + W_back(256x128)@wa + b_back.
// k-tile 32, 4 k-iterations. A smem [128 c][40 bf16], B smem [128 px][40 bf16].
// dyn smem: 4*(10240+10240) = 81920 B. grid = (576, 2).
// ---------------------------------------------------------------------------
__global__ __launch_bounds__(256, 2) void pass3_gemm(
    const float* __restrict__ x,
    const float* __restrict__ b_back,
    float* __restrict__ out)
{
    extern __shared__ __align__(16) float sm[];
    float (*stage)[132] = (float(*)[132])sm;

    const int tid = threadIdx.x;
    const int lane = tid & 31;
    const int warp = tid >> 5;
    const int warp_m = warp >> 2;
    const int warp_n = warp & 3;
    const int q = lane >> 2;
    const int kl = lane & 3;

    const int p0 = blockIdx.x * 128;
    const int b = p0 / HWSZ;
    const int hw0 = p0 % HWSZ;
    const int c0 = blockIdx.y * 128;

    float acc[4][4][4];
#pragma unroll
    for (int mt = 0; mt < 4; ++mt)
#pragma unroll
        for (int nt = 0; nt < 4; ++nt)
#pragma unroll
            for (int i = 0; i < 4; ++i) acc[mt][nt][i] = 0.f;

    const int am = tid >> 1;
    const int ah = tid & 1;

    const uint32_t as_base = (uint32_t)__cvta_generic_to_shared(sm);
    const uint32_t bs_base = as_base + 40960u;
    const uint32_t a_dst0 = as_base + (uint32_t)(am * 80 + ah * 32);
    const uint32_t b_dst0 = bs_base + (uint32_t)(am * 80 + ah * 32);
    const __nv_bfloat16* a_src0 = g_wbb + (size_t)(c0 + am) * C_O + ah * 16;
    const __nv_bfloat16* b_src0 = g_wab + (size_t)(p0 + am) * C_O + ah * 16;

    const uint32_t a_frag = as_base + (uint32_t)((warp_m * 64 + (lane & 15)) * 80
                                                 + (lane >> 4) * 16);
    const uint32_t b_frag = bs_base + (uint32_t)((warp_n * 32 + (lane & 7)) * 80
                                                 + ((lane >> 3) & 1) * 16);

#define P3_ISSUE(buf, k0) do { \
    const __nv_bfloat16* as_ = a_src0 + (k0); \
    uint32_t ad_ = a_dst0 + (uint32_t)(buf) * 10240u; \
    CP16_CA(ad_,      as_); \
    CP16_CA(ad_ + 16, as_ + 8); \
    const __nv_bfloat16* bs_ = b_src0 + (k0); \
    uint32_t bd_ = b_dst0 + (uint32_t)(buf) * 10240u; \
    CP16_CG(bd_,      bs_); \
    CP16_CG(bd_ + 16, bs_ + 8); \
} while (0)

    P3_ISSUE(0, 0);  CP_COMMIT();
    P3_ISSUE(1, 32); CP_COMMIT();
    P3_ISSUE(2, 64); CP_COMMIT();

#pragma unroll
    for (int kt = 0; kt < 4; ++kt) {
        const int buf = kt & 3;
        CP_WAIT2();
        __syncthreads();
        if (kt + 3 < 4) P3_ISSUE((kt + 3) & 3, (kt + 3) * 32);
        CP_COMMIT();

#pragma unroll
        for (int ks = 0; ks < 2; ++ks) {
            uint32_t af[4][4];
#pragma unroll
            for (int mt = 0; mt < 4; ++mt)
                ldsm_x4(af[mt][0], af[mt][1], af[mt][2], af[mt][3],
                        a_frag + (uint32_t)buf * 10240u + (uint32_t)mt * 1280u
                               + (uint32_t)ks * 32u);
            uint32_t bf[4][2];
#pragma unroll
            for (int nt = 0; nt < 4; ++nt)
                ldsm_x2(bf[nt][0], bf[nt][1],
                        b_frag + (uint32_t)buf * 10240u + (uint32_t)nt * 640u
                               + (uint32_t)ks * 32u);
#pragma unroll
            for (int mt = 0; mt < 4; ++mt)
#pragma unroll
                for (int nt = 0; nt < 4; ++nt)
                    mma_bf16(acc[mt][nt], af[mt][0], af[mt][1], af[mt][2], af[mt][3],
                             bf[nt][0], bf[nt][1]);
        }
        __syncthreads();
    }
#undef P3_ISSUE

    // Epilogue: stage [ch][px], then coalesced residual-add + store
#pragma unroll
    for (int h = 0; h < 2; ++h) {
        __syncthreads();
        if (warp_m == h) {
#pragma unroll
            for (int mt = 0; mt < 4; ++mt)
#pragma unroll
                for (int nt = 0; nt < 4; ++nt)
#pragma unroll
                    for (int hi = 0; hi < 2; ++hi) {
                        int ch = mt * 16 + q + 8 * hi;
                        int px = warp_n * 32 + nt * 8 + 2 * kl;
                        float2 v2 = make_float2(acc[mt][nt][hi * 2], acc[mt][nt][hi * 2 + 1]);
                        *(float2*)&stage[ch][px] = v2;
                    }
        }
        __syncthreads();
#pragma unroll
        for (int it = 0; it < 8; ++it) {
            int g = tid + it * 256;
            int ch = g >> 5;
            int f  = g & 31;
            int c  = c0 + h * 64 + ch;
            size_t gi = (((size_t)(b * C_IN + c)) * HWSZ + hw0) / 4 + f;
            float4 s = *(float4*)&stage[ch][f * 4];
            float4 xv = ((const float4*)x)[gi];
            float bb = b_back[c];
            float4 o4;
            o4.x = xv.x + bb + s.x;
            o4.y = xv.y + bb + s.y;
            o4.z = xv.z + bb + s.z;
            o4.w = xv.w + bb + s.w;
            ((float4*)out)[gi] = o4;
        }
    }
}

// ---------------------------------------------------------------------------
extern "C" void kernel_launch(void* const* d_in, const int* in_sizes, int n_in,
                              void* d_out, int out_size)
{
    const float* x       = (const float*)d_in[0];
    const float* w_theta = (const float*)d_in[1];
    const float* b_theta = (const float*)d_in[2];
    const float* w_phi   = (const float*)d_in[3];
    const float* b_phi   = (const float*)d_in[4];
    const float* w_g     = (const float*)d_in[5];
    const float* b_g     = (const float*)d_in[6];
    const float* w_back  = (const float*)d_in[7];
    const float* b_back  = (const float*)d_in[8];
    float* out = (float*)d_out;

    const int p1_smem = 19072 * 4;   // 76288 B
    const int p3_smem = 20480 * 4;   // 81920 B
    cudaFuncSetAttribute(pass1_gemm, cudaFuncAttributeMaxDynamicSharedMemorySize, p1_smem);
    cudaFuncSetAttribute(pass3_gemm, cudaFuncAttributeMaxDynamicSharedMemorySize, p3_smem);

    cvt_weights<<<128, 256>>>(w_theta, w_phi, w_g, w_back);
    cvt_x<<<18432, 256>>>((const float4*)x);

    dim3 g1(3, P_TOT / 128, 1);
    pass1_gemm<<<g1, 256, p1_smem>>>(b_theta, b_phi, b_g);

    pass2_attn<<<P_TOT / 16, 256>>>();

    dim3 g3(P_TOT / 128, 2, 1);
    pass3_gemm<<<g3, 256, p3_smem>>>(x, b_back, out);
}

// round 14
// speedup vs baseline: 1.6729x; 1.0203x over previous
#include <cuda_runtime.h>
#include <cuda_bf16.h>
#include <math.h>
#include <stdint.h>

// Problem constants
#define HH 96
#define WWID 96
#define HWSZ (HH * WWID)          // 9216
#define BATCH 8
#define P_TOT (BATCH * HWSZ)      // 73728 pixels
#define C_IN 256
#define C_O 128

// Scratch (device globals — allocation-free per harness rules)
__device__ __align__(16) float g_theta[(size_t)P_TOT * C_O];
__device__ __align__(16) float g_phi  [(size_t)P_TOT * C_O];
__device__ __align__(16) float g_g    [(size_t)P_TOT * C_O];
__device__ __align__(16) __nv_bfloat16 g_wab[(size_t)P_TOT * C_O];       // wa, bf16
__device__ __align__(16) __nv_bfloat16 g_xb [(size_t)BATCH * C_IN * HWSZ]; // x, bf16
__device__ __align__(16) __nv_bfloat16 g_w3b[3 * C_O * C_IN];            // bf16 weights
__device__ __align__(16) __nv_bfloat16 g_wbb[C_IN * C_O];                // bf16 w_back
__device__ float g_tnorm[P_TOT];
__device__ float g_pnorm[P_TOT];

__device__ __forceinline__ uint32_t pack_bf16(float lo, float hi) {
    uint32_t r;
    asm("cvt.rn.bf16x2.f32 %0, %1, %2;" : "=r"(r) : "f"(hi), "f"(lo));
    return r;
}

__device__ __forceinline__ void mma_bf16(float c[4],
                                         uint32_t a0, uint32_t a1, uint32_t a2, uint32_t a3,
                                         uint32_t b0, uint32_t b1) {
    asm volatile(
        "mma.sync.aligned.m16n8k16.row.col.f32.bf16.bf16.f32 "
        "{%0,%1,%2,%3},{%4,%5,%6,%7},{%8,%9},{%0,%1,%2,%3};"
        : "+f"(c[0]), "+f"(c[1]), "+f"(c[2]), "+f"(c[3])
        : "r"(a0), "r"(a1), "r"(a2), "r"(a3), "r"(b0), "r"(b1));
}

__device__ __forceinline__ void ldsm_x4(uint32_t& r0, uint32_t& r1, uint32_t& r2, uint32_t& r3,
                                        uint32_t addr) {
    asm volatile("ldmatrix.sync.aligned.m8n8.x4.shared.b16 {%0,%1,%2,%3}, [%4];"
                 : "=r"(r0), "=r"(r1), "=r"(r2), "=r"(r3) : "r"(addr));
}

__device__ __forceinline__ void ldsm_x2(uint32_t& r0, uint32_t& r1, uint32_t addr) {
    asm volatile("ldmatrix.sync.aligned.m8n8.x2.shared.b16 {%0,%1}, [%2];"
                 : "=r"(r0), "=r"(r1) : "r"(addr));
}

__device__ __forceinline__ void ldsm_x2_tr(uint32_t& r0, uint32_t& r1, uint32_t addr) {
    asm volatile("ldmatrix.sync.aligned.m8n8.x2.trans.shared.b16 {%0,%1}, [%2];"
                 : "=r"(r0), "=r"(r1) : "r"(addr));
}

#define CP16_CA(dst, src) \
    asm volatile("cp.async.ca.shared.global [%0], [%1], 16;" :: "r"(dst), "l"(src))
#define CP16_CG(dst, src) \
    asm volatile("cp.async.cg.shared.global [%0], [%1], 16;" :: "r"(dst), "l"(src))
#define CP_COMMIT() asm volatile("cp.async.commit_group;")
#define CP_WAIT2()  asm volatile("cp.async.wait_group 2;")

// ---------------------------------------------------------------------------
// Setup: bf16-convert weights (once) and x (once).
// ---------------------------------------------------------------------------
__global__ void cvt_weights(const float* __restrict__ wt, const float* __restrict__ wp,
                            const float* __restrict__ wg, const float* __restrict__ wb)
{
    int i = blockIdx.x * 256 + threadIdx.x;      // 0 .. 32767
    g_w3b[i]         = __float2bfloat16(wt[i]);
    g_w3b[32768 + i] = __float2bfloat16(wp[i]);
    g_w3b[65536 + i] = __float2bfloat16(wg[i]);
    g_wbb[i]         = __float2bfloat16(wb[i]);
}

__global__ void cvt_x(const float4* __restrict__ x4)
{
    size_t i = (size_t)blockIdx.x * 256 + threadIdx.x;   // 0 .. 4718591
    float4 v = x4[i];
    uint2 o;
    o.x = pack_bf16(v.x, v.y);
    o.y = pack_bf16(v.z, v.w);
    ((uint2*)g_xb)[i] = o;
}

// ---------------------------------------------------------------------------
// Pass 1 (bf16 tensor, 4-stage cp.async): theta/phi/g = W(128x256)@x + bias.
// k-tile 32 (2 x k16 MMA steps), 8 k-iterations. grid = (3, 576).
// A smem [128 m][40 bf16] (80B rows), B smem [32 k][136 bf16] (272B rows).
// Per-stage: A 10240B + B 8704B. dyn smem: 4*18944 + 512 = 76288 B.
// One barrier per k-iteration (trailing sync proven redundant).
// ---------------------------------------------------------------------------
__global__ __launch_bounds__(256, 2) void pass1_gemm(
    const float* __restrict__ b_theta, const float* __restrict__ b_phi,
    const float* __restrict__ b_g)
{
    extern __shared__ __align__(16) float sm[];
    float (*stage)[68] = (float(*)[68])sm;
    float* part = sm + 18944;          // [128] per-px sum of squares

    const int tid = threadIdx.x;
    const int lane = tid & 31;
    const int warp = tid >> 5;
    const int warp_m = warp >> 2;
    const int warp_n = warp & 3;
    const int q = lane >> 2;
    const int kl = lane & 3;

    const int wsel = blockIdx.x;
    const int p0 = blockIdx.y * 128;
    const int b = p0 / HWSZ;
    const int hw0 = p0 % HWSZ;

    const __nv_bfloat16* wsrc = g_w3b + wsel * 32768;
    const float* bias = (wsel == 0) ? b_theta : ((wsel == 1) ? b_phi : b_g);
    float* outp       = (wsel == 0) ? g_theta : ((wsel == 1) ? g_phi : g_g);

    float acc[4][4][4];
#pragma unroll
    for (int mt = 0; mt < 4; ++mt)
#pragma unroll
        for (int nt = 0; nt < 4; ++nt)
#pragma unroll
            for (int i = 0; i < 4; ++i) acc[mt][nt][i] = 0.f;

    const int am = tid >> 1;           // A row m (0..127)
    const int ah = tid & 1;            // A 32B-half within 64B row
    const int brow = tid >> 4;         // B k row (0..15; +16 for 2nd chunk)
    const int bcol = tid & 15;         // B 16B chunk along 128 px

    const uint32_t as_base = (uint32_t)__cvta_generic_to_shared(sm);
    const uint32_t bs_base = as_base + 40960u;           // 4 A stages
    const uint32_t a_dst0 = as_base + (uint32_t)(am * 80 + ah * 32);
    const uint32_t b_dst0 = bs_base + (uint32_t)(brow * 272 + bcol * 16);
    const __nv_bfloat16* a_src0 = wsrc + am * C_IN + ah * 16;
    const __nv_bfloat16* b_src0 = g_xb + (size_t)(b * C_IN + brow) * HWSZ + hw0 + bcol * 8;

    const uint32_t a_frag = as_base + (uint32_t)((warp_m * 64 + (lane & 15)) * 80
                                                 + (lane >> 4) * 16);
    const uint32_t b_frag = bs_base + (uint32_t)((lane & 15) * 272 + warp_n * 64);

#define P1_ISSUE(buf, k0) do { \
    const __nv_bfloat16* as_ = a_src0 + (k0); \
    uint32_t ad_ = a_dst0 + (uint32_t)(buf) * 10240u; \
    CP16_CA(ad_,      as_); \
    CP16_CA(ad_ + 16, as_ + 8); \
    const __nv_bfloat16* bs_ = b_src0 + (size_t)(k0) * HWSZ; \
    uint32_t bd_ = b_dst0 + (uint32_t)(buf) * 8704u; \
    CP16_CG(bd_,        bs_); \
    CP16_CG(bd_ + 4352, bs_ + 16 * HWSZ); \
} while (0)

    P1_ISSUE(0, 0);  CP_COMMIT();
    P1_ISSUE(1, 32); CP_COMMIT();
    P1_ISSUE(2, 64); CP_COMMIT();

#pragma unroll 4
    for (int kt = 0; kt < 8; ++kt) {
        const int buf = kt & 3;
        CP_WAIT2();
        __syncthreads();   // all warps' data landed AND all finished compute(kt-1)
        if (kt + 3 < 8) P1_ISSUE((kt + 3) & 3, (kt + 3) * 32);
        CP_COMMIT();

#pragma unroll
        for (int ks = 0; ks < 2; ++ks) {
            uint32_t af[4][4];
#pragma unroll
            for (int mt = 0; mt < 4; ++mt)
                ldsm_x4(af[mt][0], af[mt][1], af[mt][2], af[mt][3],
                        a_frag + (uint32_t)buf * 10240u + (uint32_t)mt * 1280u
                               + (uint32_t)ks * 32u);
            uint32_t bf[4][2];
#pragma unroll
            for (int nt = 0; nt < 4; ++nt)
                ldsm_x2_tr(bf[nt][0], bf[nt][1],
                           b_frag + (uint32_t)buf * 8704u + (uint32_t)ks * 4352u
                                  + (uint32_t)nt * 16u);
#pragma unroll
            for (int mt = 0; mt < 4; ++mt)
#pragma unroll
                for (int nt = 0; nt < 4; ++nt)
                    mma_bf16(acc[mt][nt], af[mt][0], af[mt][1], af[mt][2], af[mt][3],
                             bf[nt][0], bf[nt][1]);
        }
    }
#undef P1_ISSUE

    float bias_v[4][2];
#pragma unroll
    for (int mt = 0; mt < 4; ++mt)
#pragma unroll
        for (int hi = 0; hi < 2; ++hi)
            bias_v[mt][hi] = bias[warp_m * 64 + mt * 16 + q + hi * 8];

    if (tid < 128) part[tid] = 0.f;

    // Epilogue: stage [px][64ch], coalesced fp32 stores + fused norm reduction
#pragma unroll
    for (int h = 0; h < 2; ++h) {
        __syncthreads();
        if (warp_m == h) {
#pragma unroll
            for (int mt = 0; mt < 4; ++mt)
#pragma unroll
                for (int nt = 0; nt < 4; ++nt)
#pragma unroll
                    for (int i = 0; i < 4; ++i) {
                        int px = warp_n * 32 + nt * 8 + 2 * kl + (i & 1);
                        int ch = mt * 16 + q + 8 * (i >> 1);
                        stage[px][ch] = acc[mt][nt][i] + bias_v[mt][i >> 1];
                    }
        }
        __syncthreads();
#pragma unroll
        for (int it = 0; it < 8; ++it) {
            int g = tid + it * 256;
            int px = g >> 4;
            int f  = g & 15;
            float4 v = *(float4*)&stage[px][f * 4];
            ((float4*)outp)[(size_t)(p0 + px) * 32 + h * 16 + f] = v;
            if (wsel < 2) {
                float sq = v.x * v.x + v.y * v.y + v.z * v.z + v.w * v.w;
                sq += __shfl_xor_sync(0xffffffffu, sq, 1);
                sq += __shfl_xor_sync(0xffffffffu, sq, 2);
                sq += __shfl_xor_sync(0xffffffffu, sq, 4);
                sq += __shfl_xor_sync(0xffffffffu, sq, 8);
                if (f == 0) part[px] += sq;   // same thread owns px across h: no race
            }
        }
    }
    __syncthreads();
    if (wsel < 2 && tid < 128) {
        float* np = (wsel == 0) ? g_tnorm : g_pnorm;
        np[p0 + tid] = sqrtf(part[tid]);
    }
}

// ---------------------------------------------------------------------------
// Pass 2: half-warp per pixel, 8 channels/lane (2 x float4).
// Butterfly reduction: 4 stages (offsets 8,4,2,1 stay within the 16-lane half)
// -> 36 shfl/warp instead of 90. wa stored as one STG.128 per lane.
// grid = P_TOT/16, block 256 (8 warps x 2 px).
// ---------------------------------------------------------------------------
__global__ __launch_bounds__(256) void pass2_attn()
{
    const int warp = threadIdx.x >> 5;
    const int lane = threadIdx.x & 31;
    const int sub  = lane >> 4;        // pixel within pair
    const int sl   = lane & 15;        // lane within half: ch 8*sl .. 8*sl+7
    const int p = (blockIdx.x * 8 + warp) * 2 + sub;
    const int b  = p / HWSZ;
    const int hw = p % HWSZ;
    const int h  = hw / WWID;
    const int w  = hw % WWID;

    const float4* th4 = (const float4*)g_theta;
    const float4* ph4 = (const float4*)g_phi;
    const float4* gg4 = (const float4*)g_g;

    float4 t0 = th4[(size_t)p * 32 + sl * 2];
    float4 t1 = th4[(size_t)p * 32 + sl * 2 + 1];
    float tn = g_tnorm[p];

    int np[9];
    float pnv[9];
#pragma unroll
    for (int n = 0; n < 9; ++n) {
        int di = n / 3 - 1, dj = n % 3 - 1;
        int hh = min(max(h + di, 0), HH - 1);
        int wn = min(max(w + dj, 0), WWID - 1);
        np[n] = b * HWSZ + hh * WWID + wn;
        pnv[n] = g_pnorm[np[n]];
    }

    float d[9];
#pragma unroll
    for (int n = 0; n < 9; ++n) {
        float4 a = ph4[(size_t)np[n] * 32 + sl * 2];
        float4 c = ph4[(size_t)np[n] * 32 + sl * 2 + 1];
        d[n] = t0.x * a.x + t0.y * a.y + t0.z * a.z + t0.w * a.w
             + t1.x * c.x + t1.y * c.y + t1.z * c.z + t1.w * c.w;
    }
#pragma unroll
    for (int off = 8; off; off >>= 1)
#pragma unroll
        for (int n = 0; n < 9; ++n)
            d[n] += __shfl_xor_sync(0xffffffffu, d[n], off);

    // scores + softmax (bounded in [-1,1]: no max-shift needed)
    float s = 0.f;
#pragma unroll
    for (int n = 0; n < 9; ++n) {
        d[n] = __expf(d[n] / fmaxf(tn * pnv[n], 1e-8f));
        s += d[n];
    }
    float inv = 1.f / s;

    float4 a0 = make_float4(0.f, 0.f, 0.f, 0.f);
    float4 a1 = make_float4(0.f, 0.f, 0.f, 0.f);
#pragma unroll
    for (int n = 0; n < 9; ++n) {
        float wgt = d[n] * inv;
        float4 a = gg4[(size_t)np[n] * 32 + sl * 2];
        float4 c = gg4[(size_t)np[n] * 32 + sl * 2 + 1];
        a0.x += wgt * a.x; a0.y += wgt * a.y; a0.z += wgt * a.z; a0.w += wgt * a.w;
        a1.x += wgt * c.x; a1.y += wgt * c.y; a1.z += wgt * c.z; a1.w += wgt * c.w;
    }
    uint4 o;
    o.x = pack_bf16(a0.x, a0.y); o.y = pack_bf16(a0.z, a0.w);
    o.z = pack_bf16(a1.x, a1.y); o.w = pack_bf16(a1.z, a1.w);
    ((uint4*)g_wab)[(size_t)p * 16 + sl] = o;
}

// ---------------------------------------------------------------------------
// Pass 3 (bf16 tensor, 4-stage cp.async): out = x + W_back(256x128)@wa + b_back.
// k-tile 32, 4 k-iterations. A smem [128 c][40 bf16], B smem [128 px][40 bf16].
// dyn smem: 4*(10240+10240) = 81920 B. grid = (576, 2). One barrier per iter.
// ---------------------------------------------------------------------------
__global__ __launch_bounds__(256, 2) void pass3_gemm(
    const float* __restrict__ x,
    const float* __restrict__ b_back,
    float* __restrict__ out)
{
    extern __shared__ __align__(16) float sm[];
    float (*stage)[132] = (float(*)[132])sm;

    const int tid = threadIdx.x;
    const int lane = tid & 31;
    const int warp = tid >> 5;
    const int warp_m = warp >> 2;
    const int warp_n = warp & 3;
    const int q = lane >> 2;
    const int kl = lane & 3;

    const int p0 = blockIdx.x * 128;
    const int b = p0 / HWSZ;
    const int hw0 = p0 % HWSZ;
    const int c0 = blockIdx.y * 128;

    float acc[4][4][4];
#pragma unroll
    for (int mt = 0; mt < 4; ++mt)
#pragma unroll
        for (int nt = 0; nt < 4; ++nt)
#pragma unroll
            for (int i = 0; i < 4; ++i) acc[mt][nt][i] = 0.f;

    const int am = tid >> 1;
    const int ah = tid & 1;

    const uint32_t as_base = (uint32_t)__cvta_generic_to_shared(sm);
    const uint32_t bs_base = as_base + 40960u;
    const uint32_t a_dst0 = as_base + (uint32_t)(am * 80 + ah * 32);
    const uint32_t b_dst0 = bs_base + (uint32_t)(am * 80 + ah * 32);
    const __nv_bfloat16* a_src0 = g_wbb + (size_t)(c0 + am) * C_O + ah * 16;
    const __nv_bfloat16* b_src0 = g_wab + (size_t)(p0 + am) * C_O + ah * 16;

    const uint32_t a_frag = as_base + (uint32_t)((warp_m * 64 + (lane & 15)) * 80
                                                 + (lane >> 4) * 16);
    const uint32_t b_frag = bs_base + (uint32_t)((warp_n * 32 + (lane & 7)) * 80
                                                 + ((lane >> 3) & 1) * 16);

#define P3_ISSUE(buf, k0) do { \
    const __nv_bfloat16* as_ = a_src0 + (k0); \
    uint32_t ad_ = a_dst0 + (uint32_t)(buf) * 10240u; \
    CP16_CA(ad_,      as_); \
    CP16_CA(ad_ + 16, as_ + 8); \
    const __nv_bfloat16* bs_ = b_src0 + (k0); \
    uint32_t bd_ = b_dst0 + (uint32_t)(buf) * 10240u; \
    CP16_CG(bd_,      bs_); \
    CP16_CG(bd_ + 16, bs_ + 8); \
} while (0)

    P3_ISSUE(0, 0);  CP_COMMIT();
    P3_ISSUE(1, 32); CP_COMMIT();
    P3_ISSUE(2, 64); CP_COMMIT();

#pragma unroll
    for (int kt = 0; kt < 4; ++kt) {
        const int buf = kt & 3;
        CP_WAIT2();
        __syncthreads();
        if (kt + 3 < 4) P3_ISSUE((kt + 3) & 3, (kt + 3) * 32);
        CP_COMMIT();

#pragma unroll
        for (int ks = 0; ks < 2; ++ks) {
            uint32_t af[4][4];
#pragma unroll
            for (int mt = 0; mt < 4; ++mt)
                ldsm_x4(af[mt][0], af[mt][1], af[mt][2], af[mt][3],
                        a_frag + (uint32_t)buf * 10240u + (uint32_t)mt * 1280u
                               + (uint32_t)ks * 32u);
            uint32_t bf[4][2];
#pragma unroll
            for (int nt = 0; nt < 4; ++nt)
                ldsm_x2(bf[nt][0], bf[nt][1],
                        b_frag + (uint32_t)buf * 10240u + (uint32_t)nt * 640u
                               + (uint32_t)ks * 32u);
#pragma unroll
            for (int mt = 0; mt < 4; ++mt)
#pragma unroll
                for (int nt = 0; nt < 4; ++nt)
                    mma_bf16(acc[mt][nt], af[mt][0], af[mt][1], af[mt][2], af[mt][3],
                             bf[nt][0], bf[nt][1]);
        }
    }
#undef P3_ISSUE

    // Epilogue: stage [ch][px], then coalesced residual-add + store
#pragma unroll
    for (int h = 0; h < 2; ++h) {
        __syncthreads();
        if (warp_m == h) {
#pragma unroll
            for (int mt = 0; mt < 4; ++mt)
#pragma unroll
                for (int nt = 0; nt < 4; ++nt)
#pragma unroll
                    for (int hi = 0; hi < 2; ++hi) {
                        int ch = mt * 16 + q + 8 * hi;
                        int px = warp_n * 32 + nt * 8 + 2 * kl;
                        float2 v2 = make_float2(acc[mt][nt][hi * 2], acc[mt][nt][hi * 2 + 1]);
                        *(float2*)&stage[ch][px] = v2;
                    }
        }
        __syncthreads();
#pragma unroll
        for (int it = 0; it < 8; ++it) {
            int g = tid + it * 256;
            int ch = g >> 5;
            int f  = g & 31;
            int c  = c0 + h * 64 + ch;
            size_t gi = (((size_t)(b * C_IN + c)) * HWSZ + hw0) / 4 + f;
            float4 s = *(float4*)&stage[ch][f * 4];
            float4 xv = ((const float4*)x)[gi];
            float bb = b_back[c];
            float4 o4;
            o4.x = xv.x + bb + s.x;
            o4.y = xv.y + bb + s.y;
            o4.z = xv.z + bb + s.z;
            o4.w = xv.w + bb + s.w;
            ((float4*)out)[gi] = o4;
        }
    }
}

// ---------------------------------------------------------------------------
extern "C" void kernel_launch(void* const* d_in, const int* in_sizes, int n_in,
                              void* d_out, int out_size)
{
    const float* x       = (const float*)d_in[0];
    const float* w_theta = (const float*)d_in[1];
    const float* b_theta = (const float*)d_in[2];
    const float* w_phi   = (const float*)d_in[3];
    const float* b_phi   = (const float*)d_in[4];
    const float* w_g     = (const float*)d_in[5];
    const float* b_g     = (const float*)d_in[6];
    const float* w_back  = (const float*)d_in[7];
    const float* b_back  = (const float*)d_in[8];
    float* out = (float*)d_out;

    const int p1_smem = 19072 * 4;   // 76288 B
    const int p3_smem = 20480 * 4;   // 81920 B
    cudaFuncSetAttribute(pass1_gemm, cudaFuncAttributeMaxDynamicSharedMemorySize, p1_smem);
    cudaFuncSetAttribute(pass3_gemm, cudaFuncAttributeMaxDynamicSharedMemorySize, p3_smem);

    cvt_weights<<<128, 256>>>(w_theta, w_phi, w_g, w_back);
    cvt_x<<<18432, 256>>>((const float4*)x);

    dim3 g1(3, P_TOT / 128, 1);
    pass1_gemm<<<g1, 256, p1_smem>>>(b_theta, b_phi, b_g);

    pass2_attn<<<P_TOT / 16, 256>>>();

    dim3 g3(P_TOT / 128, 2, 1);
    pass3_gemm<<<g3, 256, p3_smem>>>(x, b_back, out);
}

// round 15
// speedup vs baseline: 1.7299x; 1.0340x over previous
#include <cuda_runtime.h>
#include <cuda_bf16.h>
#include <math.h>
#include <stdint.h>

// Problem constants
#define HH 96
#define WWID 96
#define HWSZ (HH * WWID)          // 9216
#define BATCH 8
#define P_TOT (BATCH * HWSZ)      // 73728 pixels
#define C_IN 256
#define C_O 128

// Scratch (device globals — allocation-free per harness rules)
__device__ __align__(16) float g_theta[(size_t)P_TOT * C_O];
__device__ __align__(16) float g_phi  [(size_t)P_TOT * C_O];
__device__ __align__(16) float g_g    [(size_t)P_TOT * C_O];
__device__ __align__(16) __nv_bfloat16 g_wab[(size_t)P_TOT * C_O];       // wa, bf16
__device__ __align__(16) __nv_bfloat16 g_xb [(size_t)BATCH * C_IN * HWSZ]; // x, bf16
__device__ __align__(16) __nv_bfloat16 g_w3b[3 * C_O * C_IN];            // bf16 weights
__device__ __align__(16) __nv_bfloat16 g_wbb[C_IN * C_O];                // bf16 w_back
__device__ float g_tnorm[P_TOT];
__device__ float g_pnorm[P_TOT];

__device__ __forceinline__ uint32_t pack_bf16(float lo, float hi) {
    uint32_t r;
    asm("cvt.rn.bf16x2.f32 %0, %1, %2;" : "=r"(r) : "f"(hi), "f"(lo));
    return r;
}

__device__ __forceinline__ void mma_bf16(float c[4],
                                         uint32_t a0, uint32_t a1, uint32_t a2, uint32_t a3,
                                         uint32_t b0, uint32_t b1) {
    asm volatile(
        "mma.sync.aligned.m16n8k16.row.col.f32.bf16.bf16.f32 "
        "{%0,%1,%2,%3},{%4,%5,%6,%7},{%8,%9},{%0,%1,%2,%3};"
        : "+f"(c[0]), "+f"(c[1]), "+f"(c[2]), "+f"(c[3])
        : "r"(a0), "r"(a1), "r"(a2), "r"(a3), "r"(b0), "r"(b1));
}

__device__ __forceinline__ void ldsm_x4(uint32_t& r0, uint32_t& r1, uint32_t& r2, uint32_t& r3,
                                        uint32_t addr) {
    asm volatile("ldmatrix.sync.aligned.m8n8.x4.shared.b16 {%0,%1,%2,%3}, [%4];"
                 : "=r"(r0), "=r"(r1), "=r"(r2), "=r"(r3) : "r"(addr));
}

__device__ __forceinline__ void ldsm_x2(uint32_t& r0, uint32_t& r1, uint32_t addr) {
    asm volatile("ldmatrix.sync.aligned.m8n8.x2.shared.b16 {%0,%1}, [%2];"
                 : "=r"(r0), "=r"(r1) : "r"(addr));
}

__device__ __forceinline__ void ldsm_x2_tr(uint32_t& r0, uint32_t& r1, uint32_t addr) {
    asm volatile("ldmatrix.sync.aligned.m8n8.x2.trans.shared.b16 {%0,%1}, [%2];"
                 : "=r"(r0), "=r"(r1) : "r"(addr));
}

#define CP16_CA(dst, src) \
    asm volatile("cp.async.ca.shared.global [%0], [%1], 16;" :: "r"(dst), "l"(src))
#define CP16_CG(dst, src) \
    asm volatile("cp.async.cg.shared.global [%0], [%1], 16;" :: "r"(dst), "l"(src))
#define CP_COMMIT() asm volatile("cp.async.commit_group;")
#define CP_WAIT2()  asm volatile("cp.async.wait_group 2;")

// ---------------------------------------------------------------------------
// Setup: bf16-convert weights (once) and x (once).
// ---------------------------------------------------------------------------
__global__ void cvt_weights(const float* __restrict__ wt, const float* __restrict__ wp,
                            const float* __restrict__ wg, const float* __restrict__ wb)
{
    int i = blockIdx.x * 256 + threadIdx.x;      // 0 .. 32767
    g_w3b[i]         = __float2bfloat16(wt[i]);
    g_w3b[32768 + i] = __float2bfloat16(wp[i]);
    g_w3b[65536 + i] = __float2bfloat16(wg[i]);
    g_wbb[i]         = __float2bfloat16(wb[i]);
}

__global__ void cvt_x(const float4* __restrict__ x4)
{
    size_t i = (size_t)blockIdx.x * 256 + threadIdx.x;   // 0 .. 4718591
    float4 v = x4[i];
    uint2 o;
    o.x = pack_bf16(v.x, v.y);
    o.y = pack_bf16(v.z, v.w);
    ((uint2*)g_xb)[i] = o;
}

// ---------------------------------------------------------------------------
// Pass 1 (bf16 tensor, 4-stage cp.async): theta/phi/g = W(128x256)@x + bias.
// k-tile 32 (2 x k16 MMA steps), 8 k-iterations. grid = (3, 576).
// A smem [128 m][40 bf16] (80B rows), B smem [32 k][136 bf16] (272B rows).
// Per-stage: A 10240B + B 8704B. dyn smem: 4*18944 + 512 = 76288 B.
// ---------------------------------------------------------------------------
__global__ __launch_bounds__(256, 2) void pass1_gemm(
    const float* __restrict__ b_theta, const float* __restrict__ b_phi,
    const float* __restrict__ b_g)
{
    extern __shared__ __align__(16) float sm[];
    float (*stage)[68] = (float(*)[68])sm;
    float* part = sm + 18944;          // [128] per-px sum of squares

    const int tid = threadIdx.x;
    const int lane = tid & 31;
    const int warp = tid >> 5;
    const int warp_m = warp >> 2;
    const int warp_n = warp & 3;
    const int q = lane >> 2;
    const int kl = lane & 3;

    const int wsel = blockIdx.x;
    const int p0 = blockIdx.y * 128;
    const int b = p0 / HWSZ;
    const int hw0 = p0 % HWSZ;

    const __nv_bfloat16* wsrc = g_w3b + wsel * 32768;
    const float* bias = (wsel == 0) ? b_theta : ((wsel == 1) ? b_phi : b_g);
    float* outp       = (wsel == 0) ? g_theta : ((wsel == 1) ? g_phi : g_g);

    float acc[4][4][4];
#pragma unroll
    for (int mt = 0; mt < 4; ++mt)
#pragma unroll
        for (int nt = 0; nt < 4; ++nt)
#pragma unroll
            for (int i = 0; i < 4; ++i) acc[mt][nt][i] = 0.f;

    const int am = tid >> 1;           // A row m (0..127)
    const int ah = tid & 1;            // A 32B-half within 64B row
    const int brow = tid >> 4;         // B k row (0..15; +16 for 2nd chunk)
    const int bcol = tid & 15;         // B 16B chunk along 128 px

    const uint32_t as_base = (uint32_t)__cvta_generic_to_shared(sm);
    const uint32_t bs_base = as_base + 40960u;           // 4 A stages
    const uint32_t a_dst0 = as_base + (uint32_t)(am * 80 + ah * 32);
    const uint32_t b_dst0 = bs_base + (uint32_t)(brow * 272 + bcol * 16);
    const __nv_bfloat16* a_src0 = wsrc + am * C_IN + ah * 16;
    const __nv_bfloat16* b_src0 = g_xb + (size_t)(b * C_IN + brow) * HWSZ + hw0 + bcol * 8;

    const uint32_t a_frag = as_base + (uint32_t)((warp_m * 64 + (lane & 15)) * 80
                                                 + (lane >> 4) * 16);
    const uint32_t b_frag = bs_base + (uint32_t)((lane & 15) * 272 + warp_n * 64);

#define P1_ISSUE(buf, k0) do { \
    const __nv_bfloat16* as_ = a_src0 + (k0); \
    uint32_t ad_ = a_dst0 + (uint32_t)(buf) * 10240u; \
    CP16_CA(ad_,      as_); \
    CP16_CA(ad_ + 16, as_ + 8); \
    const __nv_bfloat16* bs_ = b_src0 + (size_t)(k0) * HWSZ; \
    uint32_t bd_ = b_dst0 + (uint32_t)(buf) * 8704u; \
    CP16_CG(bd_,        bs_); \
    CP16_CG(bd_ + 4352, bs_ + 16 * HWSZ); \
} while (0)

    P1_ISSUE(0, 0);  CP_COMMIT();
    P1_ISSUE(1, 32); CP_COMMIT();
    P1_ISSUE(2, 64); CP_COMMIT();

#pragma unroll 4
    for (int kt = 0; kt < 8; ++kt) {
        const int buf = kt & 3;
        CP_WAIT2();
        __syncthreads();   // all warps' data landed AND all finished compute(kt-1)
        if (kt + 3 < 8) P1_ISSUE((kt + 3) & 3, (kt + 3) * 32);
        CP_COMMIT();

#pragma unroll
        for (int ks = 0; ks < 2; ++ks) {
            uint32_t af[4][4];
#pragma unroll
            for (int mt = 0; mt < 4; ++mt)
                ldsm_x4(af[mt][0], af[mt][1], af[mt][2], af[mt][3],
                        a_frag + (uint32_t)buf * 10240u + (uint32_t)mt * 1280u
                               + (uint32_t)ks * 32u);
            uint32_t bf[4][2];
#pragma unroll
            for (int nt = 0; nt < 4; ++nt)
                ldsm_x2_tr(bf[nt][0], bf[nt][1],
                           b_frag + (uint32_t)buf * 8704u + (uint32_t)ks * 4352u
                                  + (uint32_t)nt * 16u);
#pragma unroll
            for (int mt = 0; mt < 4; ++mt)
#pragma unroll
                for (int nt = 0; nt < 4; ++nt)
                    mma_bf16(acc[mt][nt], af[mt][0], af[mt][1], af[mt][2], af[mt][3],
                             bf[nt][0], bf[nt][1]);
        }
    }
#undef P1_ISSUE

    float bias_v[4][2];
#pragma unroll
    for (int mt = 0; mt < 4; ++mt)
#pragma unroll
        for (int hi = 0; hi < 2; ++hi)
            bias_v[mt][hi] = bias[warp_m * 64 + mt * 16 + q + hi * 8];

    if (tid < 128) part[tid] = 0.f;

    // Epilogue: stage [px][64ch], coalesced fp32 stores + fused norm reduction
#pragma unroll
    for (int h = 0; h < 2; ++h) {
        __syncthreads();
        if (warp_m == h) {
#pragma unroll
            for (int mt = 0; mt < 4; ++mt)
#pragma unroll
                for (int nt = 0; nt < 4; ++nt)
#pragma unroll
                    for (int i = 0; i < 4; ++i) {
                        int px = warp_n * 32 + nt * 8 + 2 * kl + (i & 1);
                        int ch = mt * 16 + q + 8 * (i >> 1);
                        stage[px][ch] = acc[mt][nt][i] + bias_v[mt][i >> 1];
                    }
        }
        __syncthreads();
#pragma unroll
        for (int it = 0; it < 8; ++it) {
            int g = tid + it * 256;
            int px = g >> 4;
            int f  = g & 15;
            float4 v = *(float4*)&stage[px][f * 4];
            ((float4*)outp)[(size_t)(p0 + px) * 32 + h * 16 + f] = v;
            if (wsel < 2) {
                float sq = v.x * v.x + v.y * v.y + v.z * v.z + v.w * v.w;
                sq += __shfl_xor_sync(0xffffffffu, sq, 1);
                sq += __shfl_xor_sync(0xffffffffu, sq, 2);
                sq += __shfl_xor_sync(0xffffffffu, sq, 4);
                sq += __shfl_xor_sync(0xffffffffu, sq, 8);
                if (f == 0) part[px] += sq;   // same thread owns px across h: no race
            }
        }
    }
    __syncthreads();
    if (wsel < 2 && tid < 128) {
        float* np = (wsel == 0) ? g_tnorm : g_pnorm;
        np[p0 + tid] = sqrtf(part[tid]);
    }
}

// ---------------------------------------------------------------------------
// Pass 2: half-warp per pixel, 8 channels/lane as float4 [sl] and [sl+16]
// (contiguous within each load -> every LDG.128 100% coalesced per half-warp).
// Butterfly: 4 stages within the 16-lane half. grid = P_TOT/16, block 256.
// ---------------------------------------------------------------------------
__global__ __launch_bounds__(256) void pass2_attn()
{
    const int warp = threadIdx.x >> 5;
    const int lane = threadIdx.x & 31;
    const int sub  = lane >> 4;        // pixel within pair
    const int sl   = lane & 15;        // lane within half
    const int p = (blockIdx.x * 8 + warp) * 2 + sub;
    const int b  = p / HWSZ;
    const int hw = p % HWSZ;
    const int h  = hw / WWID;
    const int w  = hw % WWID;

    const float4* th4 = (const float4*)g_theta;
    const float4* ph4 = (const float4*)g_phi;
    const float4* gg4 = (const float4*)g_g;

    float4 t0 = th4[(size_t)p * 32 + sl];        // channels 4sl..4sl+3
    float4 t1 = th4[(size_t)p * 32 + 16 + sl];   // channels 64+4sl..64+4sl+3
    float tn = g_tnorm[p];

    int np[9];
    float pnv[9];
#pragma unroll
    for (int n = 0; n < 9; ++n) {
        int di = n / 3 - 1, dj = n % 3 - 1;
        int hh = min(max(h + di, 0), HH - 1);
        int wn = min(max(w + dj, 0), WWID - 1);
        np[n] = b * HWSZ + hh * WWID + wn;
        pnv[n] = g_pnorm[np[n]];
    }

    float d[9];
#pragma unroll
    for (int n = 0; n < 9; ++n) {
        float4 a = ph4[(size_t)np[n] * 32 + sl];
        float4 c = ph4[(size_t)np[n] * 32 + 16 + sl];
        d[n] = t0.x * a.x + t0.y * a.y + t0.z * a.z + t0.w * a.w
             + t1.x * c.x + t1.y * c.y + t1.z * c.z + t1.w * c.w;
    }
#pragma unroll
    for (int off = 8; off; off >>= 1)
#pragma unroll
        for (int n = 0; n < 9; ++n)
            d[n] += __shfl_xor_sync(0xffffffffu, d[n], off);

    // scores + softmax (bounded in [-1,1]: no max-shift needed)
    float s = 0.f;
#pragma unroll
    for (int n = 0; n < 9; ++n) {
        d[n] = __expf(d[n] / fmaxf(tn * pnv[n], 1e-8f));
        s += d[n];
    }
    float inv = 1.f / s;

    float4 a0 = make_float4(0.f, 0.f, 0.f, 0.f);
    float4 a1 = make_float4(0.f, 0.f, 0.f, 0.f);
#pragma unroll
    for (int n = 0; n < 9; ++n) {
        float wgt = d[n] * inv;
        float4 a = gg4[(size_t)np[n] * 32 + sl];
        float4 c = gg4[(size_t)np[n] * 32 + 16 + sl];
        a0.x += wgt * a.x; a0.y += wgt * a.y; a0.z += wgt * a.z; a0.w += wgt * a.w;
        a1.x += wgt * c.x; a1.y += wgt * c.y; a1.z += wgt * c.z; a1.w += wgt * c.w;
    }
    uint2 o0, o1;
    o0.x = pack_bf16(a0.x, a0.y); o0.y = pack_bf16(a0.z, a0.w);
    o1.x = pack_bf16(a1.x, a1.y); o1.y = pack_bf16(a1.z, a1.w);
    ((uint2*)g_wab)[(size_t)p * 32 + sl]      = o0;   // 8B x 16 lanes contiguous
    ((uint2*)g_wab)[(size_t)p * 32 + 16 + sl] = o1;
}

// ---------------------------------------------------------------------------
// Pass 3 (bf16 tensor, 4-stage cp.async): out = x + W_back(256x128)@wa + b_back.
// k-tile 32, 4 k-iterations. A smem [128 c][40 bf16], B smem [128 px][40 bf16].
// dyn smem: 4*(10240+10240) = 81920 B. grid = (576, 2).
// ---------------------------------------------------------------------------
__global__ __launch_bounds__(256, 2) void pass3_gemm(
    const float* __restrict__ x,
    const float* __restrict__ b_back,
    float* __restrict__ out)
{
    extern __shared__ __align__(16) float sm[];
    float (*stage)[132] = (float(*)[132])sm;

    const int tid = threadIdx.x;
    const int lane = tid & 31;
    const int warp = tid >> 5;
    const int warp_m = warp >> 2;
    const int warp_n = warp & 3;
    const int q = lane >> 2;
    const int kl = lane & 3;

    const int p0 = blockIdx.x * 128;
    const int b = p0 / HWSZ;
    const int hw0 = p0 % HWSZ;
    const int c0 = blockIdx.y * 128;

    float acc[4][4][4];
#pragma unroll
    for (int mt = 0; mt < 4; ++mt)
#pragma unroll
        for (int nt = 0; nt < 4; ++nt)
#pragma unroll
            for (int i = 0; i < 4; ++i) acc[mt][nt][i] = 0.f;

    const int am = tid >> 1;
    const int ah = tid & 1;

    const uint32_t as_base = (uint32_t)__cvta_generic_to_shared(sm);
    const uint32_t bs_base = as_base + 40960u;
    const uint32_t a_dst0 = as_base + (uint32_t)(am * 80 + ah * 32);
    const uint32_t b_dst0 = bs_base + (uint32_t)(am * 80 + ah * 32);
    const __nv_bfloat16* a_src0 = g_wbb + (size_t)(c0 + am) * C_O + ah * 16;
    const __nv_bfloat16* b_src0 = g_wab + (size_t)(p0 + am) * C_O + ah * 16;

    const uint32_t a_frag = as_base + (uint32_t)((warp_m * 64 + (lane & 15)) * 80
                                                 + (lane >> 4) * 16);
    const uint32_t b_frag = bs_base + (uint32_t)((warp_n * 32 + (lane & 7)) * 80
                                                 + ((lane >> 3) & 1) * 16);

#define P3_ISSUE(buf, k0) do { \
    const __nv_bfloat16* as_ = a_src0 + (k0); \
    uint32_t ad_ = a_dst0 + (uint32_t)(buf) * 10240u; \
    CP16_CA(ad_,      as_); \
    CP16_CA(ad_ + 16, as_ + 8); \
    const __nv_bfloat16* bs_ = b_src0 + (k0); \
    uint32_t bd_ = b_dst0 + (uint32_t)(buf) * 10240u; \
    CP16_CG(bd_,      bs_); \
    CP16_CG(bd_ + 16, bs_ + 8); \
} while (0)

    P3_ISSUE(0, 0);  CP_COMMIT();
    P3_ISSUE(1, 32); CP_COMMIT();
    P3_ISSUE(2, 64); CP_COMMIT();

#pragma unroll
    for (int kt = 0; kt < 4; ++kt) {
        const int buf = kt & 3;
        CP_WAIT2();
        __syncthreads();
        if (kt + 3 < 4) P3_ISSUE((kt + 3) & 3, (kt + 3) * 32);
        CP_COMMIT();

#pragma unroll
        for (int ks = 0; ks < 2; ++ks) {
            uint32_t af[4][4];
#pragma unroll
            for (int mt = 0; mt < 4; ++mt)
                ldsm_x4(af[mt][0], af[mt][1], af[mt][2], af[mt][3],
                        a_frag + (uint32_t)buf * 10240u + (uint32_t)mt * 1280u
                               + (uint32_t)ks * 32u);
            uint32_t bf[4][2];
#pragma unroll
            for (int nt = 0; nt < 4; ++nt)
                ldsm_x2(bf[nt][0], bf[nt][1],
                        b_frag + (uint32_t)buf * 10240u + (uint32_t)nt * 640u
                               + (uint32_t)ks * 32u);
#pragma unroll
            for (int mt = 0; mt < 4; ++mt)
#pragma unroll
                for (int nt = 0; nt < 4; ++nt)
                    mma_bf16(acc[mt][nt], af[mt][0], af[mt][1], af[mt][2], af[mt][3],
                             bf[nt][0], bf[nt][1]);
        }
    }
#undef P3_ISSUE

    // Epilogue: stage [ch][px], then coalesced residual-add + store
#pragma unroll
    for (int h = 0; h < 2; ++h) {
        __syncthreads();
        if (warp_m == h) {
#pragma unroll
            for (int mt = 0; mt < 4; ++mt)
#pragma unroll
                for (int nt = 0; nt < 4; ++nt)
#pragma unroll
                    for (int hi = 0; hi < 2; ++hi) {
                        int ch = mt * 16 + q + 8 * hi;
                        int px = warp_n * 32 + nt * 8 + 2 * kl;
                        float2 v2 = make_float2(acc[mt][nt][hi * 2], acc[mt][nt][hi * 2 + 1]);
                        *(float2*)&stage[ch][px] = v2;
                    }
        }
        __syncthreads();
#pragma unroll
        for (int it = 0; it < 8; ++it) {
            int g = tid + it * 256;
            int ch = g >> 5;
            int f  = g & 31;
            int c  = c0 + h * 64 + ch;
            size_t gi = (((size_t)(b * C_IN + c)) * HWSZ + hw0) / 4 + f;
            float4 s = *(float4*)&stage[ch][f * 4];
            float4 xv = ((const float4*)x)[gi];
            float bb = b_back[c];
            float4 o4;
            o4.x = xv.x + bb + s.x;
            o4.y = xv.y + bb + s.y;
            o4.z = xv.z + bb + s.z;
            o4.w = xv.w + bb + s.w;
            ((float4*)out)[gi] = o4;
        }
    }
}

// ---------------------------------------------------------------------------
extern "C" void kernel_launch(void* const* d_in, const int* in_sizes, int n_in,
                              void* d_out, int out_size)
{
    const float* x       = (const float*)d_in[0];
    const float* w_theta = (const float*)d_in[1];
    const float* b_theta = (const float*)d_in[2];
    const float* w_phi   = (const float*)d_in[3];
    const float* b_phi   = (const float*)d_in[4];
    const float* w_g     = (const float*)d_in[5];
    const float* b_g     = (const float*)d_in[6];
    const float* w_back  = (const float*)d_in[7];
    const float* b_back  = (const float*)d_in[8];
    float* out = (float*)d_out;

    const int p1_smem = 19072 * 4;   // 76288 B
    const int p3_smem = 20480 * 4;   // 81920 B
    cudaFuncSetAttribute(pass1_gemm, cudaFuncAttributeMaxDynamicSharedMemorySize, p1_smem);
    cudaFuncSetAttribute(pass3_gemm, cudaFuncAttributeMaxDynamicSharedMemorySize, p3_smem);

    cvt_weights<<<128, 256>>>(w_theta, w_phi, w_g, w_back);
    cvt_x<<<18432, 256>>>((const float4*)x);

    dim3 g1(3, P_TOT / 128, 1);
    pass1_gemm<<<g1, 256, p1_smem>>>(b_theta, b_phi, b_g);

    pass2_attn<<<P_TOT / 16, 256>>>();

    dim3 g3(P_TOT / 128, 2, 1);
    pass3_gemm<<<g3, 256, p3_smem>>>(x, b_back, out);
}

// round 16
// speedup vs baseline: 1.7979x; 1.0393x over previous
#include <cuda_runtime.h>
#include <cuda_bf16.h>
#include <math.h>
#include <stdint.h>

// Problem constants
#define HH 96
#define WWID 96
#define HWSZ (HH * WWID)          // 9216
#define BATCH 8
#define P_TOT (BATCH * HWSZ)      // 73728 pixels
#define C_IN 256
#define C_O 128

// Scratch (device globals — allocation-free per harness rules)
__device__ __align__(16) float g_theta[(size_t)P_TOT * C_O];   // normalized
__device__ __align__(16) float g_phi  [(size_t)P_TOT * C_O];   // normalized
__device__ __align__(16) float g_g    [(size_t)P_TOT * C_O];
__device__ __align__(16) __nv_bfloat16 g_wab[(size_t)P_TOT * C_O];       // wa, bf16
__device__ __align__(16) __nv_bfloat16 g_xb [(size_t)BATCH * C_IN * HWSZ]; // x, bf16
__device__ __align__(16) __nv_bfloat16 g_w3b[3 * C_O * C_IN];            // bf16 weights
__device__ __align__(16) __nv_bfloat16 g_wbb[C_IN * C_O];                // bf16 w_back

__device__ __forceinline__ uint32_t pack_bf16(float lo, float hi) {
    uint32_t r;
    asm("cvt.rn.bf16x2.f32 %0, %1, %2;" : "=r"(r) : "f"(hi), "f"(lo));
    return r;
}

__device__ __forceinline__ void mma_bf16(float c[4],
                                         uint32_t a0, uint32_t a1, uint32_t a2, uint32_t a3,
                                         uint32_t b0, uint32_t b1) {
    asm volatile(
        "mma.sync.aligned.m16n8k16.row.col.f32.bf16.bf16.f32 "
        "{%0,%1,%2,%3},{%4,%5,%6,%7},{%8,%9},{%0,%1,%2,%3};"
        : "+f"(c[0]), "+f"(c[1]), "+f"(c[2]), "+f"(c[3])
        : "r"(a0), "r"(a1), "r"(a2), "r"(a3), "r"(b0), "r"(b1));
}

__device__ __forceinline__ void ldsm_x4(uint32_t& r0, uint32_t& r1, uint32_t& r2, uint32_t& r3,
                                        uint32_t addr) {
    asm volatile("ldmatrix.sync.aligned.m8n8.x4.shared.b16 {%0,%1,%2,%3}, [%4];"
                 : "=r"(r0), "=r"(r1), "=r"(r2), "=r"(r3) : "r"(addr));
}

__device__ __forceinline__ void ldsm_x2(uint32_t& r0, uint32_t& r1, uint32_t addr) {
    asm volatile("ldmatrix.sync.aligned.m8n8.x2.shared.b16 {%0,%1}, [%2];"
                 : "=r"(r0), "=r"(r1) : "r"(addr));
}

__device__ __forceinline__ void ldsm_x2_tr(uint32_t& r0, uint32_t& r1, uint32_t addr) {
    asm volatile("ldmatrix.sync.aligned.m8n8.x2.trans.shared.b16 {%0,%1}, [%2];"
                 : "=r"(r0), "=r"(r1) : "r"(addr));
}

#define CP16_CA(dst, src) \
    asm volatile("cp.async.ca.shared.global [%0], [%1], 16;" :: "r"(dst), "l"(src))
#define CP16_CG(dst, src) \
    asm volatile("cp.async.cg.shared.global [%0], [%1], 16;" :: "r"(dst), "l"(src))
#define CP_COMMIT() asm volatile("cp.async.commit_group;")
#define CP_WAIT2()  asm volatile("cp.async.wait_group 2;")

// ---------------------------------------------------------------------------
// Setup: bf16-convert x and weights in ONE launch.
// ---------------------------------------------------------------------------
__global__ void cvt_all(const float4* __restrict__ x4,
                        const float* __restrict__ wt, const float* __restrict__ wp,
                        const float* __restrict__ wg, const float* __restrict__ wb)
{
    size_t i = (size_t)blockIdx.x * 256 + threadIdx.x;   // 0 .. 4718591
    float4 v = x4[i];
    uint2 o;
    o.x = pack_bf16(v.x, v.y);
    o.y = pack_bf16(v.z, v.w);
    ((uint2*)g_xb)[i] = o;
    if (i < 32768) {
        g_w3b[i]         = __float2bfloat16(wt[i]);
        g_w3b[32768 + i] = __float2bfloat16(wp[i]);
        g_w3b[65536 + i] = __float2bfloat16(wg[i]);
        g_wbb[i]         = __float2bfloat16(wb[i]);
    }
}

// ---------------------------------------------------------------------------
// Pass 1 (bf16 tensor, 4-stage cp.async): theta/phi/g = W(128x256)@x + bias.
// k-tile 32 (2 x k16 MMA steps), 8 k-iterations. grid = (3, 576).
// theta & phi are L2-NORMALIZED in the epilogue (cosine-sim pre-division).
// dyn smem: 4*18944 + 512 = 76288 B.
// ---------------------------------------------------------------------------
__global__ __launch_bounds__(256, 2) void pass1_gemm(
    const float* __restrict__ b_theta, const float* __restrict__ b_phi,
    const float* __restrict__ b_g)
{
    extern __shared__ __align__(16) float sm[];
    float (*stage)[68] = (float(*)[68])sm;
    float* part = sm + 18944;          // [128] per-px sum of squares -> inv norm

    const int tid = threadIdx.x;
    const int lane = tid & 31;
    const int warp = tid >> 5;
    const int warp_m = warp >> 2;
    const int warp_n = warp & 3;
    const int q = lane >> 2;
    const int kl = lane & 3;

    const int wsel = blockIdx.x;
    const int p0 = blockIdx.y * 128;
    const int b = p0 / HWSZ;
    const int hw0 = p0 % HWSZ;

    const __nv_bfloat16* wsrc = g_w3b + wsel * 32768;
    const float* bias = (wsel == 0) ? b_theta : ((wsel == 1) ? b_phi : b_g);
    float* outp       = (wsel == 0) ? g_theta : ((wsel == 1) ? g_phi : g_g);

    float acc[4][4][4];
#pragma unroll
    for (int mt = 0; mt < 4; ++mt)
#pragma unroll
        for (int nt = 0; nt < 4; ++nt)
#pragma unroll
            for (int i = 0; i < 4; ++i) acc[mt][nt][i] = 0.f;

    const int am = tid >> 1;           // A row m (0..127)
    const int ah = tid & 1;            // A 32B-half within 64B row
    const int brow = tid >> 4;         // B k row (0..15; +16 for 2nd chunk)
    const int bcol = tid & 15;         // B 16B chunk along 128 px

    const uint32_t as_base = (uint32_t)__cvta_generic_to_shared(sm);
    const uint32_t bs_base = as_base + 40960u;           // 4 A stages
    const uint32_t a_dst0 = as_base + (uint32_t)(am * 80 + ah * 32);
    const uint32_t b_dst0 = bs_base + (uint32_t)(brow * 272 + bcol * 16);
    const __nv_bfloat16* a_src0 = wsrc + am * C_IN + ah * 16;
    const __nv_bfloat16* b_src0 = g_xb + (size_t)(b * C_IN + brow) * HWSZ + hw0 + bcol * 8;

    const uint32_t a_frag = as_base + (uint32_t)((warp_m * 64 + (lane & 15)) * 80
                                                 + (lane >> 4) * 16);
    const uint32_t b_frag = bs_base + (uint32_t)((lane & 15) * 272 + warp_n * 64);

#define P1_ISSUE(buf, k0) do { \
    const __nv_bfloat16* as_ = a_src0 + (k0); \
    uint32_t ad_ = a_dst0 + (uint32_t)(buf) * 10240u; \
    CP16_CA(ad_,      as_); \
    CP16_CA(ad_ + 16, as_ + 8); \
    const __nv_bfloat16* bs_ = b_src0 + (size_t)(k0) * HWSZ; \
    uint32_t bd_ = b_dst0 + (uint32_t)(buf) * 8704u; \
    CP16_CG(bd_,        bs_); \
    CP16_CG(bd_ + 4352, bs_ + 16 * HWSZ); \
} while (0)

    P1_ISSUE(0, 0);  CP_COMMIT();
    P1_ISSUE(1, 32); CP_COMMIT();
    P1_ISSUE(2, 64); CP_COMMIT();

#pragma unroll 4
    for (int kt = 0; kt < 8; ++kt) {
        const int buf = kt & 3;
        CP_WAIT2();
        __syncthreads();   // all warps' data landed AND all finished compute(kt-1)
        if (kt + 3 < 8) P1_ISSUE((kt + 3) & 3, (kt + 3) * 32);
        CP_COMMIT();

#pragma unroll
        for (int ks = 0; ks < 2; ++ks) {
            uint32_t af[4][4];
#pragma unroll
            for (int mt = 0; mt < 4; ++mt)
                ldsm_x4(af[mt][0], af[mt][1], af[mt][2], af[mt][3],
                        a_frag + (uint32_t)buf * 10240u + (uint32_t)mt * 1280u
                               + (uint32_t)ks * 32u);
            uint32_t bf[4][2];
#pragma unroll
            for (int nt = 0; nt < 4; ++nt)
                ldsm_x2_tr(bf[nt][0], bf[nt][1],
                           b_frag + (uint32_t)buf * 8704u + (uint32_t)ks * 4352u
                                  + (uint32_t)nt * 16u);
#pragma unroll
            for (int mt = 0; mt < 4; ++mt)
#pragma unroll
                for (int nt = 0; nt < 4; ++nt)
                    mma_bf16(acc[mt][nt], af[mt][0], af[mt][1], af[mt][2], af[mt][3],
                             bf[nt][0], bf[nt][1]);
        }
    }
#undef P1_ISSUE

    // add bias into accumulators
    float bias_v[4][2];
#pragma unroll
    for (int mt = 0; mt < 4; ++mt)
#pragma unroll
        for (int hi = 0; hi < 2; ++hi)
            bias_v[mt][hi] = bias[warp_m * 64 + mt * 16 + q + hi * 8];
#pragma unroll
    for (int mt = 0; mt < 4; ++mt)
#pragma unroll
        for (int nt = 0; nt < 4; ++nt)
#pragma unroll
            for (int i = 0; i < 4; ++i)
                acc[mt][nt][i] += bias_v[mt][i >> 1];

    if (wsel == 2) {
        // g: plain staged store
#pragma unroll
        for (int h = 0; h < 2; ++h) {
            __syncthreads();
            if (warp_m == h) {
#pragma unroll
                for (int mt = 0; mt < 4; ++mt)
#pragma unroll
                    for (int nt = 0; nt < 4; ++nt)
#pragma unroll
                        for (int i = 0; i < 4; ++i) {
                            int px = warp_n * 32 + nt * 8 + 2 * kl + (i & 1);
                            int ch = mt * 16 + q + 8 * (i >> 1);
                            stage[px][ch] = acc[mt][nt][i];
                        }
            }
            __syncthreads();
#pragma unroll
            for (int it = 0; it < 8; ++it) {
                int g = tid + it * 256;
                int px = g >> 4;
                int f  = g & 15;
                float4 v = *(float4*)&stage[px][f * 4];
                ((float4*)outp)[(size_t)(p0 + px) * 32 + h * 16 + f] = v;
            }
        }
    } else {
        // theta/phi: Round A computes norms, Round B stores normalized
        if (tid < 128) part[tid] = 0.f;
#pragma unroll
        for (int h = 0; h < 2; ++h) {
            __syncthreads();
            if (warp_m == h) {
#pragma unroll
                for (int mt = 0; mt < 4; ++mt)
#pragma unroll
                    for (int nt = 0; nt < 4; ++nt)
#pragma unroll
                        for (int i = 0; i < 4; ++i) {
                            int px = warp_n * 32 + nt * 8 + 2 * kl + (i & 1);
                            int ch = mt * 16 + q + 8 * (i >> 1);
                            stage[px][ch] = acc[mt][nt][i];
                        }
            }
            __syncthreads();
#pragma unroll
            for (int it = 0; it < 8; ++it) {
                int g = tid + it * 256;
                int px = g >> 4;
                int f  = g & 15;
                float4 v = *(float4*)&stage[px][f * 4];
                float sq = v.x * v.x + v.y * v.y + v.z * v.z + v.w * v.w;
                sq += __shfl_xor_sync(0xffffffffu, sq, 1);
                sq += __shfl_xor_sync(0xffffffffu, sq, 2);
                sq += __shfl_xor_sync(0xffffffffu, sq, 4);
                sq += __shfl_xor_sync(0xffffffffu, sq, 8);
                if (f == 0) part[px] += sq;   // same thread owns px across h
            }
        }
        __syncthreads();
        if (tid < 128) part[tid] = rsqrtf(fmaxf(part[tid], 1e-24f));
        // Round B: restage + scaled store
#pragma unroll
        for (int h = 0; h < 2; ++h) {
            __syncthreads();
            if (warp_m == h) {
#pragma unroll
                for (int mt = 0; mt < 4; ++mt)
#pragma unroll
                    for (int nt = 0; nt < 4; ++nt)
#pragma unroll
                        for (int i = 0; i < 4; ++i) {
                            int px = warp_n * 32 + nt * 8 + 2 * kl + (i & 1);
                            int ch = mt * 16 + q + 8 * (i >> 1);
                            stage[px][ch] = acc[mt][nt][i];
                        }
            }
            __syncthreads();
#pragma unroll
            for (int it = 0; it < 8; ++it) {
                int g = tid + it * 256;
                int px = g >> 4;
                int f  = g & 15;
                float4 v = *(float4*)&stage[px][f * 4];
                float inv = part[px];
                v.x *= inv; v.y *= inv; v.z *= inv; v.w *= inv;
                ((float4*)outp)[(size_t)(p0 + px) * 32 + h * 16 + f] = v;
            }
        }
    }
}

// ---------------------------------------------------------------------------
// Pass 2: half-warp per pixel, 8 channels/lane as float4 [sl] and [sl+16].
// theta/phi pre-normalized -> dot IS the cosine: no norm loads, no divides.
// grid = P_TOT/16, block 256 (8 warps x 2 px).
// ---------------------------------------------------------------------------
__global__ __launch_bounds__(256) void pass2_attn()
{
    const int warp = threadIdx.x >> 5;
    const int lane = threadIdx.x & 31;
    const int sub  = lane >> 4;        // pixel within pair
    const int sl   = lane & 15;        // lane within half
    const int p = (blockIdx.x * 8 + warp) * 2 + sub;
    const int b  = p / HWSZ;
    const int hw = p % HWSZ;
    const int h  = hw / WWID;
    const int w  = hw % WWID;

    const float4* th4 = (const float4*)g_theta;
    const float4* ph4 = (const float4*)g_phi;
    const float4* gg4 = (const float4*)g_g;

    float4 t0 = th4[(size_t)p * 32 + sl];
    float4 t1 = th4[(size_t)p * 32 + 16 + sl];

    int np[9];
#pragma unroll
    for (int n = 0; n < 9; ++n) {
        int di = n / 3 - 1, dj = n % 3 - 1;
        int hh = min(max(h + di, 0), HH - 1);
        int wn = min(max(w + dj, 0), WWID - 1);
        np[n] = b * HWSZ + hh * WWID + wn;
    }

    float d[9];
#pragma unroll
    for (int n = 0; n < 9; ++n) {
        float4 a = ph4[(size_t)np[n] * 32 + sl];
        float4 c = ph4[(size_t)np[n] * 32 + 16 + sl];
        d[n] = t0.x * a.x + t0.y * a.y + t0.z * a.z + t0.w * a.w
             + t1.x * c.x + t1.y * c.y + t1.z * c.z + t1.w * c.w;
    }
#pragma unroll
    for (int off = 8; off; off >>= 1)
#pragma unroll
        for (int n = 0; n < 9; ++n)
            d[n] += __shfl_xor_sync(0xffffffffu, d[n], off);

    // softmax over 9 (cosine scores bounded in [-1,1]: no max-shift needed)
    float s = 0.f;
#pragma unroll
    for (int n = 0; n < 9; ++n) {
        d[n] = __expf(d[n]);
        s += d[n];
    }
    float inv = 1.f / s;

    float4 a0 = make_float4(0.f, 0.f, 0.f, 0.f);
    float4 a1 = make_float4(0.f, 0.f, 0.f, 0.f);
#pragma unroll
    for (int n = 0; n < 9; ++n) {
        float wgt = d[n] * inv;
        float4 a = gg4[(size_t)np[n] * 32 + sl];
        float4 c = gg4[(size_t)np[n] * 32 + 16 + sl];
        a0.x += wgt * a.x; a0.y += wgt * a.y; a0.z += wgt * a.z; a0.w += wgt * a.w;
        a1.x += wgt * c.x; a1.y += wgt * c.y; a1.z += wgt * c.z; a1.w += wgt * c.w;
    }
    uint2 o0, o1;
    o0.x = pack_bf16(a0.x, a0.y); o0.y = pack_bf16(a0.z, a0.w);
    o1.x = pack_bf16(a1.x, a1.y); o1.y = pack_bf16(a1.z, a1.w);
    ((uint2*)g_wab)[(size_t)p * 32 + sl]      = o0;
    ((uint2*)g_wab)[(size_t)p * 32 + 16 + sl] = o1;
}

// ---------------------------------------------------------------------------
// Pass 3 (bf16 tensor, 4-stage cp.async): out = x + W_back(256x128)@wa + b_back.
// k-tile 32, 4 k-iterations. dyn smem: 81920 B. grid = (576, 2).
// ---------------------------------------------------------------------------
__global__ __launch_bounds__(256, 2) void pass3_gemm(
    const float* __restrict__ x,
    const float* __restrict__ b_back,
    float* __restrict__ out)
{
    extern __shared__ __align__(16) float sm[];
    float (*stage)[132] = (float(*)[132])sm;

    const int tid = threadIdx.x;
    const int lane = tid & 31;
    const int warp = tid >> 5;
    const int warp_m = warp >> 2;
    const int warp_n = warp & 3;
    const int q = lane >> 2;
    const int kl = lane & 3;

    const int p0 = blockIdx.x * 128;
    const int b = p0 / HWSZ;
    const int hw0 = p0 % HWSZ;
    const int c0 = blockIdx.y * 128;

    float acc[4][4][4];
#pragma unroll
    for (int mt = 0; mt < 4; ++mt)
#pragma unroll
        for (int nt = 0; nt < 4; ++nt)
#pragma unroll
            for (int i = 0; i < 4; ++i) acc[mt][nt][i] = 0.f;

    const int am = tid >> 1;
    const int ah = tid & 1;

    const uint32_t as_base = (uint32_t)__cvta_generic_to_shared(sm);
    const uint32_t bs_base = as_base + 40960u;
    const uint32_t a_dst0 = as_base + (uint32_t)(am * 80 + ah * 32);
    const uint32_t b_dst0 = bs_base + (uint32_t)(am * 80 + ah * 32);
    const __nv_bfloat16* a_src0 = g_wbb + (size_t)(c0 + am) * C_O + ah * 16;
    const __nv_bfloat16* b_src0 = g_wab + (size_t)(p0 + am) * C_O + ah * 16;

    const uint32_t a_frag = as_base + (uint32_t)((warp_m * 64 + (lane & 15)) * 80
                                                 + (lane >> 4) * 16);
    const uint32_t b_frag = bs_base + (uint32_t)((warp_n * 32 + (lane & 7)) * 80
                                                 + ((lane >> 3) & 1) * 16);

#define P3_ISSUE(buf, k0) do { \
    const __nv_bfloat16* as_ = a_src0 + (k0); \
    uint32_t ad_ = a_dst0 + (uint32_t)(buf) * 10240u; \
    CP16_CA(ad_,      as_); \
    CP16_CA(ad_ + 16, as_ + 8); \
    const __nv_bfloat16* bs_ = b_src0 + (k0); \
    uint32_t bd_ = b_dst0 + (uint32_t)(buf) * 10240u; \
    CP16_CG(bd_,      bs_); \
    CP16_CG(bd_ + 16, bs_ + 8); \
} while (0)

    P3_ISSUE(0, 0);  CP_COMMIT();
    P3_ISSUE(1, 32); CP_COMMIT();
    P3_ISSUE(2, 64); CP_COMMIT();

#pragma unroll
    for (int kt = 0; kt < 4; ++kt) {
        const int buf = kt & 3;
        CP_WAIT2();
        __syncthreads();
        if (kt + 3 < 4) P3_ISSUE((kt + 3) & 3, (kt + 3) * 32);
        CP_COMMIT();

#pragma unroll
        for (int ks = 0; ks < 2; ++ks) {
            uint32_t af[4][4];
#pragma unroll
            for (int mt = 0; mt < 4; ++mt)
                ldsm_x4(af[mt][0], af[mt][1], af[mt][2], af[mt][3],
                        a_frag + (uint32_t)buf * 10240u + (uint32_t)mt * 1280u
                               + (uint32_t)ks * 32u);
            uint32_t bf[4][2];
#pragma unroll
            for (int nt = 0; nt < 4; ++nt)
                ldsm_x2(bf[nt][0], bf[nt][1],
                        b_frag + (uint32_t)buf * 10240u + (uint32_t)nt * 640u
                               + (uint32_t)ks * 32u);
#pragma unroll
            for (int mt = 0; mt < 4; ++mt)
#pragma unroll
                for (int nt = 0; nt < 4; ++nt)
                    mma_bf16(acc[mt][nt], af[mt][0], af[mt][1], af[mt][2], af[mt][3],
                             bf[nt][0], bf[nt][1]);
        }
    }
#undef P3_ISSUE

    // Epilogue: stage [ch][px], then coalesced residual-add + store
#pragma unroll
    for (int h = 0; h < 2; ++h) {
        __syncthreads();
        if (warp_m == h) {
#pragma unroll
            for (int mt = 0; mt < 4; ++mt)
#pragma unroll
                for (int nt = 0; nt < 4; ++nt)
#pragma unroll
                    for (int hi = 0; hi < 2; ++hi) {
                        int ch = mt * 16 + q + 8 * hi;
                        int px = warp_n * 32 + nt * 8 + 2 * kl;
                        float2 v2 = make_float2(acc[mt][nt][hi * 2], acc[mt][nt][hi * 2 + 1]);
                        *(float2*)&stage[ch][px] = v2;
                    }
        }
        __syncthreads();
#pragma unroll
        for (int it = 0; it < 8; ++it) {
            int g = tid + it * 256;
            int ch = g >> 5;
            int f  = g & 31;
            int c  = c0 + h * 64 + ch;
            size_t gi = (((size_t)(b * C_IN + c)) * HWSZ + hw0) / 4 + f;
            float4 s = *(float4*)&stage[ch][f * 4];
            float4 xv = ((const float4*)x)[gi];
            float bb = b_back[c];
            float4 o4;
            o4.x = xv.x + bb + s.x;
            o4.y = xv.y + bb + s.y;
            o4.z = xv.z + bb + s.z;
            o4.w = xv.w + bb + s.w;
            ((float4*)out)[gi] = o4;
        }
    }
}

// ---------------------------------------------------------------------------
extern "C" void kernel_launch(void* const* d_in, const int* in_sizes, int n_in,
                              void* d_out, int out_size)
{
    const float* x       = (const float*)d_in[0];
    const float* w_theta = (const float*)d_in[1];
    const float* b_theta = (const float*)d_in[2];
    const float* w_phi   = (const float*)d_in[3];
    const float* b_phi   = (const float*)d_in[4];
    const float* w_g     = (const float*)d_in[5];
    const float* b_g     = (const float*)d_in[6];
    const float* w_back  = (const float*)d_in[7];
    const float* b_back  = (const float*)d_in[8];
    float* out = (float*)d_out;

    const int p1_smem = 19072 * 4;   // 76288 B
    const int p3_smem = 20480 * 4;   // 81920 B
    cudaFuncSetAttribute(pass1_gemm, cudaFuncAttributeMaxDynamicSharedMemorySize, p1_smem);
    cudaFuncSetAttribute(pass3_gemm, cudaFuncAttributeMaxDynamicSharedMemorySize, p3_smem);

    cvt_all<<<18432, 256>>>((const float4*)x, w_theta, w_phi, w_g, w_back);

    dim3 g1(3, P_TOT / 128, 1);
    pass1_gemm<<<g1, 256, p1_smem>>>(b_theta, b_phi, b_g);

    pass2_attn<<<P_TOT / 16, 256>>>();

    dim3 g3(P_TOT / 128, 2, 1);
    pass3_gemm<<<g3, 256, p3_smem>>>(x, b_back, out);
}

// round 17
// speedup vs baseline: 1.8122x; 1.0080x over previous
#include <cuda_runtime.h>
#include <cuda_bf16.h>
#include <math.h>
#include <stdint.h>

// Problem constants
#define HH 96
#define WWID 96
#define HWSZ (HH * WWID)          // 9216
#define BATCH 8
#define P_TOT (BATCH * HWSZ)      // 73728 pixels
#define C_IN 256
#define C_O 128

// Scratch (device globals — allocation-free per harness rules)
__device__ __align__(16) float g_theta[(size_t)P_TOT * C_O];   // normalized
__device__ __align__(16) float g_phi  [(size_t)P_TOT * C_O];   // normalized
__device__ __align__(16) float g_g    [(size_t)P_TOT * C_O];
__device__ __align__(16) __nv_bfloat16 g_wab[(size_t)P_TOT * C_O];       // wa, bf16
__device__ __align__(16) __nv_bfloat16 g_xb [(size_t)BATCH * C_IN * HWSZ]; // x, bf16
__device__ __align__(16) __nv_bfloat16 g_w3b[3 * C_O * C_IN];            // bf16 weights
__device__ __align__(16) __nv_bfloat16 g_wbb[C_IN * C_O];                // bf16 w_back

__device__ __forceinline__ uint32_t pack_bf16(float lo, float hi) {
    uint32_t r;
    asm("cvt.rn.bf16x2.f32 %0, %1, %2;" : "=r"(r) : "f"(hi), "f"(lo));
    return r;
}

__device__ __forceinline__ void mma_bf16(float c[4],
                                         uint32_t a0, uint32_t a1, uint32_t a2, uint32_t a3,
                                         uint32_t b0, uint32_t b1) {
    asm volatile(
        "mma.sync.aligned.m16n8k16.row.col.f32.bf16.bf16.f32 "
        "{%0,%1,%2,%3},{%4,%5,%6,%7},{%8,%9},{%0,%1,%2,%3};"
        : "+f"(c[0]), "+f"(c[1]), "+f"(c[2]), "+f"(c[3])
        : "r"(a0), "r"(a1), "r"(a2), "r"(a3), "r"(b0), "r"(b1));
}

__device__ __forceinline__ void ldsm_x4(uint32_t& r0, uint32_t& r1, uint32_t& r2, uint32_t& r3,
                                        uint32_t addr) {
    asm volatile("ldmatrix.sync.aligned.m8n8.x4.shared.b16 {%0,%1,%2,%3}, [%4];"
                 : "=r"(r0), "=r"(r1), "=r"(r2), "=r"(r3) : "r"(addr));
}

__device__ __forceinline__ void ldsm_x2(uint32_t& r0, uint32_t& r1, uint32_t addr) {
    asm volatile("ldmatrix.sync.aligned.m8n8.x2.shared.b16 {%0,%1}, [%2];"
                 : "=r"(r0), "=r"(r1) : "r"(addr));
}

__device__ __forceinline__ void ldsm_x2_tr(uint32_t& r0, uint32_t& r1, uint32_t addr) {
    asm volatile("ldmatrix.sync.aligned.m8n8.x2.trans.shared.b16 {%0,%1}, [%2];"
                 : "=r"(r0), "=r"(r1) : "r"(addr));
}

#define CP16_CA(dst, src) \
    asm volatile("cp.async.ca.shared.global [%0], [%1], 16;" :: "r"(dst), "l"(src))
#define CP16_CG(dst, src) \
    asm volatile("cp.async.cg.shared.global [%0], [%1], 16;" :: "r"(dst), "l"(src))
#define CP_COMMIT() asm volatile("cp.async.commit_group;")
#define CP_WAIT2()  asm volatile("cp.async.wait_group 2;")
#define CP_WAITN(n) asm volatile("cp.async.wait_group %0;" :: "n"(n))

// ---------------------------------------------------------------------------
// Setup: bf16-convert x and weights in ONE launch.
// ---------------------------------------------------------------------------
__global__ void cvt_all(const float4* __restrict__ x4,
                        const float* __restrict__ wt, const float* __restrict__ wp,
                        const float* __restrict__ wg, const float* __restrict__ wb)
{
    size_t i = (size_t)blockIdx.x * 256 + threadIdx.x;   // 0 .. 4718591
    float4 v = x4[i];
    uint2 o;
    o.x = pack_bf16(v.x, v.y);
    o.y = pack_bf16(v.z, v.w);
    ((uint2*)g_xb)[i] = o;
    if (i < 32768) {
        g_w3b[i]         = __float2bfloat16(wt[i]);
        g_w3b[32768 + i] = __float2bfloat16(wp[i]);
        g_w3b[65536 + i] = __float2bfloat16(wg[i]);
        g_wbb[i]         = __float2bfloat16(wb[i]);
    }
}

// ---------------------------------------------------------------------------
// Pass 1 (bf16 tensor, 4-stage cp.async): theta/phi/g = W(128x256)@x + bias.
// k-tile 32 (2 x k16 MMA steps), 8 k-iterations. grid = (3, 576).
// theta & phi are L2-NORMALIZED in the epilogue (cosine-sim pre-division).
// dyn smem: 4*18944 + 512 = 76288 B.
// ---------------------------------------------------------------------------
__global__ __launch_bounds__(256, 2) void pass1_gemm(
    const float* __restrict__ b_theta, const float* __restrict__ b_phi,
    const float* __restrict__ b_g)
{
    extern __shared__ __align__(16) float sm[];
    float (*stage)[68] = (float(*)[68])sm;
    float* part = sm + 18944;          // [128] per-px sum of squares -> inv norm

    const int tid = threadIdx.x;
    const int lane = tid & 31;
    const int warp = tid >> 5;
    const int warp_m = warp >> 2;
    const int warp_n = warp & 3;
    const int q = lane >> 2;
    const int kl = lane & 3;

    const int wsel = blockIdx.x;
    const int p0 = blockIdx.y * 128;
    const int b = p0 / HWSZ;
    const int hw0 = p0 % HWSZ;

    const __nv_bfloat16* wsrc = g_w3b + wsel * 32768;
    const float* bias = (wsel == 0) ? b_theta : ((wsel == 1) ? b_phi : b_g);
    float* outp       = (wsel == 0) ? g_theta : ((wsel == 1) ? g_phi : g_g);

    float acc[4][4][4];
#pragma unroll
    for (int mt = 0; mt < 4; ++mt)
#pragma unroll
        for (int nt = 0; nt < 4; ++nt)
#pragma unroll
            for (int i = 0; i < 4; ++i) acc[mt][nt][i] = 0.f;

    const int am = tid >> 1;           // A row m (0..127)
    const int ah = tid & 1;            // A 32B-half within 64B row
    const int brow = tid >> 4;         // B k row (0..15; +16 for 2nd chunk)
    const int bcol = tid & 15;         // B 16B chunk along 128 px

    const uint32_t as_base = (uint32_t)__cvta_generic_to_shared(sm);
    const uint32_t bs_base = as_base + 40960u;           // 4 A stages
    const uint32_t a_dst0 = as_base + (uint32_t)(am * 80 + ah * 32);
    const uint32_t b_dst0 = bs_base + (uint32_t)(brow * 272 + bcol * 16);
    const __nv_bfloat16* a_src0 = wsrc + am * C_IN + ah * 16;
    const __nv_bfloat16* b_src0 = g_xb + (size_t)(b * C_IN + brow) * HWSZ + hw0 + bcol * 8;

    const uint32_t a_frag = as_base + (uint32_t)((warp_m * 64 + (lane & 15)) * 80
                                                 + (lane >> 4) * 16);
    const uint32_t b_frag = bs_base + (uint32_t)((lane & 15) * 272 + warp_n * 64);

#define P1_ISSUE(buf, k0) do { \
    const __nv_bfloat16* as_ = a_src0 + (k0); \
    uint32_t ad_ = a_dst0 + (uint32_t)(buf) * 10240u; \
    CP16_CA(ad_,      as_); \
    CP16_CA(ad_ + 16, as_ + 8); \
    const __nv_bfloat16* bs_ = b_src0 + (size_t)(k0) * HWSZ; \
    uint32_t bd_ = b_dst0 + (uint32_t)(buf) * 8704u; \
    CP16_CG(bd_,        bs_); \
    CP16_CG(bd_ + 4352, bs_ + 16 * HWSZ); \
} while (0)

    P1_ISSUE(0, 0);  CP_COMMIT();
    P1_ISSUE(1, 32); CP_COMMIT();
    P1_ISSUE(2, 64); CP_COMMIT();

#pragma unroll 4
    for (int kt = 0; kt < 8; ++kt) {
        const int buf = kt & 3;
        CP_WAIT2();
        __syncthreads();   // all warps' data landed AND all finished compute(kt-1)
        if (kt + 3 < 8) P1_ISSUE((kt + 3) & 3, (kt + 3) * 32);
        CP_COMMIT();

#pragma unroll
        for (int ks = 0; ks < 2; ++ks) {
            uint32_t af[4][4];
#pragma unroll
            for (int mt = 0; mt < 4; ++mt)
                ldsm_x4(af[mt][0], af[mt][1], af[mt][2], af[mt][3],
                        a_frag + (uint32_t)buf * 10240u + (uint32_t)mt * 1280u
                               + (uint32_t)ks * 32u);
            uint32_t bf[4][2];
#pragma unroll
            for (int nt = 0; nt < 4; ++nt)
                ldsm_x2_tr(bf[nt][0], bf[nt][1],
                           b_frag + (uint32_t)buf * 8704u + (uint32_t)ks * 4352u
                                  + (uint32_t)nt * 16u);
#pragma unroll
            for (int mt = 0; mt < 4; ++mt)
#pragma unroll
                for (int nt = 0; nt < 4; ++nt)
                    mma_bf16(acc[mt][nt], af[mt][0], af[mt][1], af[mt][2], af[mt][3],
                             bf[nt][0], bf[nt][1]);
        }
    }
#undef P1_ISSUE

    // add bias into accumulators
    float bias_v[4][2];
#pragma unroll
    for (int mt = 0; mt < 4; ++mt)
#pragma unroll
        for (int hi = 0; hi < 2; ++hi)
            bias_v[mt][hi] = bias[warp_m * 64 + mt * 16 + q + hi * 8];
#pragma unroll
    for (int mt = 0; mt < 4; ++mt)
#pragma unroll
        for (int nt = 0; nt < 4; ++nt)
#pragma unroll
            for (int i = 0; i < 4; ++i)
                acc[mt][nt][i] += bias_v[mt][i >> 1];

    if (wsel == 2) {
        // g: plain staged store
#pragma unroll
        for (int h = 0; h < 2; ++h) {
            __syncthreads();
            if (warp_m == h) {
#pragma unroll
                for (int mt = 0; mt < 4; ++mt)
#pragma unroll
                    for (int nt = 0; nt < 4; ++nt)
#pragma unroll
                        for (int i = 0; i < 4; ++i) {
                            int px = warp_n * 32 + nt * 8 + 2 * kl + (i & 1);
                            int ch = mt * 16 + q + 8 * (i >> 1);
                            stage[px][ch] = acc[mt][nt][i];
                        }
            }
            __syncthreads();
#pragma unroll
            for (int it = 0; it < 8; ++it) {
                int g = tid + it * 256;
                int px = g >> 4;
                int f  = g & 15;
                float4 v = *(float4*)&stage[px][f * 4];
                ((float4*)outp)[(size_t)(p0 + px) * 32 + h * 16 + f] = v;
            }
        }
    } else {
        // theta/phi: Round A computes norms, Round B stores normalized
        if (tid < 128) part[tid] = 0.f;
#pragma unroll
        for (int h = 0; h < 2; ++h) {
            __syncthreads();
            if (warp_m == h) {
#pragma unroll
                for (int mt = 0; mt < 4; ++mt)
#pragma unroll
                    for (int nt = 0; nt < 4; ++nt)
#pragma unroll
                        for (int i = 0; i < 4; ++i) {
                            int px = warp_n * 32 + nt * 8 + 2 * kl + (i & 1);
                            int ch = mt * 16 + q + 8 * (i >> 1);
                            stage[px][ch] = acc[mt][nt][i];
                        }
            }
            __syncthreads();
#pragma unroll
            for (int it = 0; it < 8; ++it) {
                int g = tid + it * 256;
                int px = g >> 4;
                int f  = g & 15;
                float4 v = *(float4*)&stage[px][f * 4];
                float sq = v.x * v.x + v.y * v.y + v.z * v.z + v.w * v.w;
                sq += __shfl_xor_sync(0xffffffffu, sq, 1);
                sq += __shfl_xor_sync(0xffffffffu, sq, 2);
                sq += __shfl_xor_sync(0xffffffffu, sq, 4);
                sq += __shfl_xor_sync(0xffffffffu, sq, 8);
                if (f == 0) part[px] += sq;   // same thread owns px across h
            }
        }
        __syncthreads();
        if (tid < 128) part[tid] = rsqrtf(fmaxf(part[tid], 1e-24f));
        // Round B: restage + scaled store
#pragma unroll
        for (int h = 0; h < 2; ++h) {
            __syncthreads();
            if (warp_m == h) {
#pragma unroll
                for (int mt = 0; mt < 4; ++mt)
#pragma unroll
                    for (int nt = 0; nt < 4; ++nt)
#pragma unroll
                        for (int i = 0; i < 4; ++i) {
                            int px = warp_n * 32 + nt * 8 + 2 * kl + (i & 1);
                            int ch = mt * 16 + q + 8 * (i >> 1);
                            stage[px][ch] = acc[mt][nt][i];
                        }
            }
            __syncthreads();
#pragma unroll
            for (int it = 0; it < 8; ++it) {
                int g = tid + it * 256;
                int px = g >> 4;
                int f  = g & 15;
                float4 v = *(float4*)&stage[px][f * 4];
                float inv = part[px];
                v.x *= inv; v.y *= inv; v.z *= inv; v.w *= inv;
                ((float4*)outp)[(size_t)(p0 + px) * 32 + h * 16 + f] = v;
            }
        }
    }
}

// ---------------------------------------------------------------------------
// Pass 2: half-warp per pixel, 8 channels/lane as float4 [sl] and [sl+16].
// theta/phi pre-normalized -> dot IS the cosine: no norm loads, no divides.
// grid = P_TOT/16, block 256 (8 warps x 2 px).
// ---------------------------------------------------------------------------
__global__ __launch_bounds__(256) void pass2_attn()
{
    const int warp = threadIdx.x >> 5;
    const int lane = threadIdx.x & 31;
    const int sub  = lane >> 4;        // pixel within pair
    const int sl   = lane & 15;        // lane within half
    const int p = (blockIdx.x * 8 + warp) * 2 + sub;
    const int b  = p / HWSZ;
    const int hw = p % HWSZ;
    const int h  = hw / WWID;
    const int w  = hw % WWID;

    const float4* th4 = (const float4*)g_theta;
    const float4* ph4 = (const float4*)g_phi;
    const float4* gg4 = (const float4*)g_g;

    float4 t0 = th4[(size_t)p * 32 + sl];
    float4 t1 = th4[(size_t)p * 32 + 16 + sl];

    int np[9];
#pragma unroll
    for (int n = 0; n < 9; ++n) {
        int di = n / 3 - 1, dj = n % 3 - 1;
        int hh = min(max(h + di, 0), HH - 1);
        int wn = min(max(w + dj, 0), WWID - 1);
        np[n] = b * HWSZ + hh * WWID + wn;
    }

    float d[9];
#pragma unroll
    for (int n = 0; n < 9; ++n) {
        float4 a = ph4[(size_t)np[n] * 32 + sl];
        float4 c = ph4[(size_t)np[n] * 32 + 16 + sl];
        d[n] = t0.x * a.x + t0.y * a.y + t0.z * a.z + t0.w * a.w
             + t1.x * c.x + t1.y * c.y + t1.z * c.z + t1.w * c.w;
    }
#pragma unroll
    for (int off = 8; off; off >>= 1)
#pragma unroll
        for (int n = 0; n < 9; ++n)
            d[n] += __shfl_xor_sync(0xffffffffu, d[n], off);

    // softmax over 9 (cosine scores bounded in [-1,1]: no max-shift needed)
    float s = 0.f;
#pragma unroll
    for (int n = 0; n < 9; ++n) {
        d[n] = __expf(d[n]);
        s += d[n];
    }
    float inv = 1.f / s;

    float4 a0 = make_float4(0.f, 0.f, 0.f, 0.f);
    float4 a1 = make_float4(0.f, 0.f, 0.f, 0.f);
#pragma unroll
    for (int n = 0; n < 9; ++n) {
        float wgt = d[n] * inv;
        float4 a = gg4[(size_t)np[n] * 32 + sl];
        float4 c = gg4[(size_t)np[n] * 32 + 16 + sl];
        a0.x += wgt * a.x; a0.y += wgt * a.y; a0.z += wgt * a.z; a0.w += wgt * a.w;
        a1.x += wgt * c.x; a1.y += wgt * c.y; a1.z += wgt * c.z; a1.w += wgt * c.w;
    }
    uint2 o0, o1;
    o0.x = pack_bf16(a0.x, a0.y); o0.y = pack_bf16(a0.z, a0.w);
    o1.x = pack_bf16(a1.x, a1.y); o1.y = pack_bf16(a1.z, a1.w);
    ((uint2*)g_wab)[(size_t)p * 32 + sl]      = o0;
    ((uint2*)g_wab)[(size_t)p * 32 + 16 + sl] = o1;
}

// ---------------------------------------------------------------------------
// Pass 3 (bf16 tensor): out = x + W_back(256x128)@wa + b_back.
// All 4 k-tiles issued up-front (groups 0-3) + x residual h=0 (group 4);
// x h=1 streamed during the h=0 store round. Epilogue reads x from smem.
// dyn smem: ring 81920 + xbuf 32768 = 114688 B. grid = (576, 2).
// ---------------------------------------------------------------------------
__global__ __launch_bounds__(256, 2) void pass3_gemm(
    const float* __restrict__ x,
    const float* __restrict__ b_back,
    float* __restrict__ out)
{
    extern __shared__ __align__(16) float sm[];
    float (*stage)[132] = (float(*)[132])sm;     // 64ch x 132 = 33792B (<= 40960)
    float* xbuf0 = sm + 20480;                   // byte 81920..114687
    float* xbuf1 = sm + 10240;                   // byte 40960..73727 (dead ring)

    const int tid = threadIdx.x;
    const int lane = tid & 31;
    const int warp = tid >> 5;
    const int warp_m = warp >> 2;
    const int warp_n = warp & 3;
    const int q = lane >> 2;
    const int kl = lane & 3;

    const int p0 = blockIdx.x * 128;
    const int b = p0 / HWSZ;
    const int hw0 = p0 % HWSZ;
    const int c0 = blockIdx.y * 128;

    float acc[4][4][4];
#pragma unroll
    for (int mt = 0; mt < 4; ++mt)
#pragma unroll
        for (int nt = 0; nt < 4; ++nt)
#pragma unroll
            for (int i = 0; i < 4; ++i) acc[mt][nt][i] = 0.f;

    const int am = tid >> 1;
    const int ah = tid & 1;

    const uint32_t as_base = (uint32_t)__cvta_generic_to_shared(sm);
    const uint32_t bs_base = as_base + 40960u;
    const uint32_t a_dst0 = as_base + (uint32_t)(am * 80 + ah * 32);
    const uint32_t b_dst0 = bs_base + (uint32_t)(am * 80 + ah * 32);
    const __nv_bfloat16* a_src0 = g_wbb + (size_t)(c0 + am) * C_O + ah * 16;
    const __nv_bfloat16* b_src0 = g_wab + (size_t)(p0 + am) * C_O + ah * 16;

    const uint32_t a_frag = as_base + (uint32_t)((warp_m * 64 + (lane & 15)) * 80
                                                 + (lane >> 4) * 16);
    const uint32_t b_frag = bs_base + (uint32_t)((warp_n * 32 + (lane & 7)) * 80
                                                 + ((lane >> 3) & 1) * 16);

#define P3_ISSUE(buf, k0) do { \
    const __nv_bfloat16* as_ = a_src0 + (k0); \
    uint32_t ad_ = a_dst0 + (uint32_t)(buf) * 10240u; \
    CP16_CA(ad_,      as_); \
    CP16_CA(ad_ + 16, as_ + 8); \
    const __nv_bfloat16* bs_ = b_src0 + (k0); \
    uint32_t bd_ = b_dst0 + (uint32_t)(buf) * 10240u; \
    CP16_CG(bd_,      bs_); \
    CP16_CG(bd_ + 16, bs_ + 8); \
} while (0)

// x residual prefetch: 64 ch x 128 px fp32 = 32KB, 8 x 16B per thread
#define P3_XISSUE(h, smoff_bytes) do { \
    _Pragma("unroll") \
    for (int it = 0; it < 8; ++it) { \
        int idx = tid + it * 256; \
        int ch = idx >> 5; \
        int f  = idx & 31; \
        const float* src = x + (size_t)(b * C_IN + c0 + (h) * 64 + ch) * HWSZ + hw0 + f * 4; \
        CP16_CG(as_base + (uint32_t)(smoff_bytes) + (uint32_t)idx * 16u, src); \
    } \
} while (0)

    // Issue everything up-front: 4 GEMM tiles + x(h=0). 5 commit groups.
    P3_ISSUE(0, 0);   CP_COMMIT();
    P3_ISSUE(1, 32);  CP_COMMIT();
    P3_ISSUE(2, 64);  CP_COMMIT();
    P3_ISSUE(3, 96);  CP_COMMIT();
    P3_XISSUE(0, 81920); CP_COMMIT();
#undef P3_ISSUE

#define P3_STEP(kt, waitn) do { \
    CP_WAITN(waitn); \
    __syncthreads(); \
    _Pragma("unroll") \
    for (int ks = 0; ks < 2; ++ks) { \
        uint32_t af[4][4]; \
        _Pragma("unroll") \
        for (int mt = 0; mt < 4; ++mt) \
            ldsm_x4(af[mt][0], af[mt][1], af[mt][2], af[mt][3], \
                    a_frag + (uint32_t)(kt) * 10240u + (uint32_t)mt * 1280u \
                           + (uint32_t)ks * 32u); \
        uint32_t bf[4][2]; \
        _Pragma("unroll") \
        for (int nt = 0; nt < 4; ++nt) \
            ldsm_x2(bf[nt][0], bf[nt][1], \
                    b_frag + (uint32_t)(kt) * 10240u + (uint32_t)nt * 640u \
                           + (uint32_t)ks * 32u); \
        _Pragma("unroll") \
        for (int mt = 0; mt < 4; ++mt) \
            _Pragma("unroll") \
            for (int nt = 0; nt < 4; ++nt) \
                mma_bf16(acc[mt][nt], af[mt][0], af[mt][1], af[mt][2], af[mt][3], \
                         bf[nt][0], bf[nt][1]); \
    } \
} while (0)

    P3_STEP(0, 4);
    P3_STEP(1, 3);
    P3_STEP(2, 2);
    P3_STEP(3, 1);
#undef P3_STEP

    // ---- Epilogue: h=0 ----
    CP_WAITN(0);           // x(h=0) landed
    __syncthreads();       // GEMM reads of ring complete block-wide
    P3_XISSUE(1, 40960);   // stream x(h=1) into dead ring region
    CP_COMMIT();

    if (warp_m == 0) {
#pragma unroll
        for (int mt = 0; mt < 4; ++mt)
#pragma unroll
            for (int nt = 0; nt < 4; ++nt)
#pragma unroll
                for (int hi = 0; hi < 2; ++hi) {
                    int ch = mt * 16 + q + 8 * hi;
                    int px = warp_n * 32 + nt * 8 + 2 * kl;
                    float2 v2 = make_float2(acc[mt][nt][hi * 2], acc[mt][nt][hi * 2 + 1]);
                    *(float2*)&stage[ch][px] = v2;
                }
    }
    __syncthreads();
#pragma unroll
    for (int it = 0; it < 8; ++it) {
        int g = tid + it * 256;
        int ch = g >> 5;
        int f  = g & 31;
        int c  = c0 + ch;
        size_t gi = (((size_t)(b * C_IN + c)) * HWSZ + hw0) / 4 + f;
        float4 s = *(float4*)&stage[ch][f * 4];
        float4 xv = ((const float4*)xbuf0)[g];
        float bb = b_back[c];
        float4 o4;
        o4.x = xv.x + bb + s.x;
        o4.y = xv.y + bb + s.y;
        o4.z = xv.z + bb + s.z;
        o4.w = xv.w + bb + s.w;
        ((float4*)out)[gi] = o4;
    }

    // ---- Epilogue: h=1 ----
    CP_WAITN(0);           // x(h=1) landed
    __syncthreads();
    if (warp_m == 1) {
#pragma unroll
        for (int mt = 0; mt < 4; ++mt)
#pragma unroll
            for (int nt = 0; nt < 4; ++nt)
#pragma unroll
                for (int hi = 0; hi < 2; ++hi) {
                    int ch = mt * 16 + q + 8 * hi;
                    int px = warp_n * 32 + nt * 8 + 2 * kl;
                    float2 v2 = make_float2(acc[mt][nt][hi * 2], acc[mt][nt][hi * 2 + 1]);
                    *(float2*)&stage[ch][px] = v2;
                }
    }
    __syncthreads();
#pragma unroll
    for (int it = 0; it < 8; ++it) {
        int g = tid + it * 256;
        int ch = g >> 5;
        int f  = g & 31;
        int c  = c0 + 64 + ch;
        size_t gi = (((size_t)(b * C_IN + c)) * HWSZ + hw0) / 4 + f;
        float4 s = *(float4*)&stage[ch][f * 4];
        float4 xv = ((const float4*)xbuf1)[g];
        float bb = b_back[c];
        float4 o4;
        o4.x = xv.x + bb + s.x;
        o4.y = xv.y + bb + s.y;
        o4.z = xv.z + bb + s.z;
        o4.w = xv.w + bb + s.w;
        ((float4*)out)[gi] = o4;
    }
#undef P3_XISSUE
}

// ---------------------------------------------------------------------------
extern "C" void kernel_launch(void* const* d_in, const int* in_sizes, int n_in,
                              void* d_out, int out_size)
{
    const float* x       = (const float*)d_in[0];
    const float* w_theta = (const float*)d_in[1];
    const float* b_theta = (const float*)d_in[2];
    const float* w_phi   = (const float*)d_in[3];
    const float* b_phi   = (const float*)d_in[4];
    const float* w_g     = (const float*)d_in[5];
    const float* b_g     = (const float*)d_in[6];
    const float* w_back  = (const float*)d_in[7];
    const float* b_back  = (const float*)d_in[8];
    float* out = (float*)d_out;

    const int p1_smem = 19072 * 4;   // 76288 B
    const int p3_smem = 114688;      // ring 81920 + xbuf 32768
    cudaFuncSetAttribute(pass1_gemm, cudaFuncAttributeMaxDynamicSharedMemorySize, p1_smem);
    cudaFuncSetAttribute(pass3_gemm, cudaFuncAttributeMaxDynamicSharedMemorySize, p3_smem);

    cvt_all<<<18432, 256>>>((const float4*)x, w_theta, w_phi, w_g, w_back);

    dim3 g1(3, P_TOT / 128, 1);
    pass1_gemm<<<g1, 256, p1_smem>>>(b_theta, b_phi, b_g);

    pass2_attn<<<P_TOT / 16, 256>>>();

    dim3 g3(P_TOT / 128, 2, 1);
    pass3_gemm<<<g3, 256, p3_smem>>>(x, b_back, out);
}